// round 14
// baseline (speedup 1.0000x reference)
#include <cuda_runtime.h>
#include <cuda_bf16.h>
#include <cuda_fp16.h>
#include <math.h>
#include <stdint.h>

// Problem constants
#define B_   8
#define C_   256
#define H_   56
#define W_   56
#define HW_  3136        // 56*56
#define KHW_ 784         // 28*28
#define HEADS_ 8
#define NTOT_ 6422528    // B*C*HW
#define NPART_ 6272
#define BIASN_ 19668992  // HEADS*HW*KHW
#define NBIASBLK_ 9604   // BIASN/8/256
#define EPS_ 1e-5
#define SCALE_ 0.17677669529663687f   // 1/sqrt(32)
#define LOG2E_ 1.4426950408889634f

// Scratch (static device arrays — allocation-free)
__device__ __nv_bfloat16 g_q[B_ * 256 * HW_];    // [b][hd][i]  (log2e-scaled)
__device__ __nv_bfloat16 g_k[B_ * 256 * KHW_];   // [b][hd][j]
__device__ __half        g_v[B_ * 256 * KHW_];   // [b][hd][j]  fp16
__device__ __nv_bfloat16 g_res[B_ * HW_ * 256];  // [b][i][hd]
__device__ __nv_bfloat16 g_ck[B_ * C_ * KHW_];
__device__ __nv_bfloat16 g_cv[B_ * C_ * KHW_];
__device__ __nv_bfloat16 g_xbf[NTOT_];
__device__ __half        g_bbf[BIASN_];          // bias*log2e in fp16
__device__ __nv_bfloat16 g_wq[65536], g_wk[65536], g_wv[65536], g_wo[65536];
__device__ float g_part[2 * NPART_];
__device__ float g_wqsum[256];

// ---------------------------------------------------------------------------
// asm helpers
// ---------------------------------------------------------------------------
__device__ __forceinline__ uint32_t smem_u32(const void* p) {
    return (uint32_t)__cvta_generic_to_shared(p);
}
__device__ __forceinline__ void ldm_x4(uint32_t* r, uint32_t addr) {
    asm volatile("ldmatrix.sync.aligned.m8n8.x4.shared.b16 {%0,%1,%2,%3}, [%4];"
        : "=r"(r[0]), "=r"(r[1]), "=r"(r[2]), "=r"(r[3]) : "r"(addr));
}
__device__ __forceinline__ void ldm_x4_t(uint32_t* r, uint32_t addr) {
    asm volatile("ldmatrix.sync.aligned.m8n8.x4.trans.shared.b16 {%0,%1,%2,%3}, [%4];"
        : "=r"(r[0]), "=r"(r[1]), "=r"(r[2]), "=r"(r[3]) : "r"(addr));
}
__device__ __forceinline__ void mma_bf16(float* d, const uint32_t* a, const uint32_t* b) {
    asm volatile(
        "mma.sync.aligned.m16n8k16.row.col.f32.bf16.bf16.f32 "
        "{%0,%1,%2,%3}, {%4,%5,%6,%7}, {%8,%9}, {%0,%1,%2,%3};"
        : "+f"(d[0]), "+f"(d[1]), "+f"(d[2]), "+f"(d[3])
        : "r"(a[0]), "r"(a[1]), "r"(a[2]), "r"(a[3]), "r"(b[0]), "r"(b[1]));
}
__device__ __forceinline__ void mma_f16(float* d, const uint32_t* a, const uint32_t* b) {
    asm volatile(
        "mma.sync.aligned.m16n8k16.row.col.f32.f16.f16.f32 "
        "{%0,%1,%2,%3}, {%4,%5,%6,%7}, {%8,%9}, {%0,%1,%2,%3};"
        : "+f"(d[0]), "+f"(d[1]), "+f"(d[2]), "+f"(d[3])
        : "r"(a[0]), "r"(a[1]), "r"(a[2]), "r"(a[3]), "r"(b[0]), "r"(b[1]));
}
__device__ __forceinline__ uint32_t bias_ex2(float lo, float hi, uint32_t bias2) {
    uint32_t t, u, r;
    asm("cvt.rn.f16x2.f32 %0, %1, %2;" : "=r"(t) : "f"(hi), "f"(lo));
    asm("add.f16x2 %0, %1, %2;" : "=r"(u) : "r"(t), "r"(bias2));
    asm("ex2.approx.f16x2 %0, %1;" : "=r"(r) : "r"(u));
    return r;
}
__device__ __forceinline__ void cp16(uint32_t dst, const void* src) {
    asm volatile("cp.async.cg.shared.global [%0], [%1], 16;" :: "r"(dst), "l"(src));
}
__device__ __forceinline__ void cp_commit() {
    asm volatile("cp.async.commit_group;" ::: "memory");
}
__device__ __forceinline__ void cp_wait_all() {
    asm volatile("cp.async.wait_group 0;" ::: "memory");
}

// ---------------------------------------------------------------------------
// MEGA PREP: block ranges do x->bf16+LN partials | W->bf16+wqsum | bias->fp16
// ---------------------------------------------------------------------------
__global__ void prep_kernel(const float* __restrict__ x,
                            const float* __restrict__ Wq, const float* __restrict__ Wk,
                            const float* __restrict__ Wv, const float* __restrict__ Wo,
                            const float* __restrict__ Bb) {
    const int bid = blockIdx.x, tid = threadIdx.x;
    if (bid < NPART_) {
        // ---- x fp32 -> bf16 + LN partial sums ----
        int i = bid * 256 + tid;
        float4 v = ((const float4*)x)[i];
        __nv_bfloat162* o = (__nv_bfloat162*)(g_xbf + (size_t)i * 4);
        o[0] = __floats2bfloat162_rn(v.x, v.y);
        o[1] = __floats2bfloat162_rn(v.z, v.w);
        float s  = v.x + v.y + v.z + v.w;
        float ss = v.x * v.x + v.y * v.y + v.z * v.z + v.w * v.w;
        #pragma unroll
        for (int ofs = 16; ofs; ofs >>= 1) {
            s  += __shfl_xor_sync(0xffffffffu, s, ofs);
            ss += __shfl_xor_sync(0xffffffffu, ss, ofs);
        }
        __shared__ float sh[16];
        int w = tid >> 5, lane = tid & 31;
        if (lane == 0) { sh[w] = s; sh[8 + w] = ss; }
        __syncthreads();
        if (tid == 0) {
            float a = 0.f, b = 0.f;
            #pragma unroll
            for (int k = 0; k < 8; k++) { a += sh[k]; b += sh[8 + k]; }
            g_part[bid] = a;
            g_part[NPART_ + bid] = b;
        }
    } else if (bid < NPART_ + 256) {
        // ---- weight conversions + Wq rowsum (block handles one row) ----
        int r = bid - NPART_;
        int base = r * 256 + (tid & 63) * 4;
        int grp = tid >> 6;
        const float* src = (grp == 0) ? Wq : (grp == 1) ? Wk : (grp == 2) ? Wv : Wo;
        __nv_bfloat16* dst = (grp == 0) ? g_wq : (grp == 1) ? g_wk : (grp == 2) ? g_wv : g_wo;
        float4 v = *(const float4*)(src + base);
        *(__nv_bfloat162*)(dst + base)     = __floats2bfloat162_rn(v.x, v.y);
        *(__nv_bfloat162*)(dst + base + 2) = __floats2bfloat162_rn(v.z, v.w);
        float s = (grp == 0) ? (v.x + v.y) + (v.z + v.w) : 0.f;
        #pragma unroll
        for (int ofs = 16; ofs; ofs >>= 1) s += __shfl_xor_sync(0xffffffffu, s, ofs);
        __shared__ float sh2[8];
        if ((tid & 31) == 0) sh2[tid >> 5] = s;
        __syncthreads();
        if (tid == 0) g_wqsum[r] = sh2[0] + sh2[1];
    } else {
        // ---- bias fp32 -> fp16 * log2e ----
        size_t i = (size_t)(bid - NPART_ - 256) * 256 + tid;
        float4 a = ((const float4*)Bb)[2 * i];
        float4 b = ((const float4*)Bb)[2 * i + 1];
        __half2* o = (__half2*)(g_bbf + i * 8);
        o[0] = __floats2half2_rn(a.x * LOG2E_, a.y * LOG2E_);
        o[1] = __floats2half2_rn(a.z * LOG2E_, a.w * LOG2E_);
        o[2] = __floats2half2_rn(b.x * LOG2E_, b.y * LOG2E_);
        o[3] = __floats2half2_rn(b.z * LOG2E_, b.w * LOG2E_);
    }
}

// ---------------------------------------------------------------------------
// Depthwise 3x3 stride-2 conv (K and V paths fused), bf16 output
// ---------------------------------------------------------------------------
__global__ void dwconv_kernel(const float* __restrict__ x,
                              const float* __restrict__ wk, const float* __restrict__ bkd,
                              const float* __restrict__ wv, const float* __restrict__ bvd) {
    int idx = blockIdx.x * blockDim.x + threadIdx.x;
    if (idx >= B_ * C_ * KHW_) return;
    int ox = idx % 28;
    int oy = (idx / 28) % 28;
    int c  = (idx / KHW_) % C_;
    int b  = idx / (KHW_ * C_);
    const float* xp = x + ((size_t)(b * C_ + c)) * HW_;
    float ak = 0.f, av = 0.f;
    #pragma unroll
    for (int ky = 0; ky < 3; ky++) {
        int iy = oy * 2 + ky - 1;
        if (iy < 0 || iy >= H_) continue;
        #pragma unroll
        for (int kx = 0; kx < 3; kx++) {
            int ix = ox * 2 + kx - 1;
            if (ix < 0 || ix >= W_) continue;
            float xv = xp[iy * W_ + ix];
            ak += xv * wk[c * 9 + ky * 3 + kx];
            av += xv * wv[c * 9 + ky * 3 + kx];
        }
    }
    g_ck[idx] = __float2bfloat16(ak + bkd[c]);
    g_cv[idx] = __float2bfloat16(av + bvd[c]);
}

// ---------------------------------------------------------------------------
// FUSED Q+K+V projection GEMM (one launch).
// z: 0..7 = Q batch z (Mt=HW, stats folded in-block), 8..15 = K, 16..23 = V.
// ---------------------------------------------------------------------------
#define WST 40
#define XST 136
__global__ void __launch_bounds__(256, 2) gemm_qkv(
    const float* __restrict__ bq, const float* __restrict__ bk,
    const float* __restrict__ bv)
{
    const int z = blockIdx.z;
    const int mode = (z < 8) ? 1 : ((z < 16) ? 0 : 2);   // 1=Q, 0=K, 2=V
    const int b = z & 7;
    const int Mt = (mode == 1) ? HW_ : KHW_;
    const int P0 = blockIdx.x * 128;
    if (P0 >= Mt) return;
    const int R0 = blockIdx.y * 128;
    const __nv_bfloat16* W = (mode == 1) ? g_wq : ((mode == 0) ? g_wk : g_wv);
    const __nv_bfloat16* X = (mode == 1)
        ? (g_xbf + (size_t)b * 256 * HW_)
        : (((mode == 0) ? g_ck : g_cv) + (size_t)b * 256 * KHW_);

    const int tid = threadIdx.x, lane = tid & 31, w = tid >> 5;
    const int wR = (w >> 2) * 64, wP = (w & 3) * 32;

    // --- Q blocks: redundant in-block LN stats reduction ---
    __shared__ float s_mu, s_rstd;
    if (mode == 1) {
        double s = 0.0, ss = 0.0;
        for (int i = tid; i < NPART_; i += 256) {
            s  += (double)g_part[i];
            ss += (double)g_part[NPART_ + i];
        }
        #pragma unroll
        for (int ofs = 16; ofs; ofs >>= 1) {
            s  += __shfl_xor_sync(0xffffffffu, s, ofs);
            ss += __shfl_xor_sync(0xffffffffu, ss, ofs);
        }
        __shared__ double shs[8], shss[8];
        if (lane == 0) { shs[w] = s; shss[w] = ss; }
        __syncthreads();
        if (tid == 0) {
            double a = 0.0, c2 = 0.0;
            #pragma unroll
            for (int k = 0; k < 8; k++) { a += shs[k]; c2 += shss[k]; }
            double N = (double)NTOT_;
            double mu = a / N;
            double var = c2 / N - mu * mu;
            s_mu = (float)mu;
            s_rstd = (float)(1.0 / sqrt(var + EPS_));
        }
        __syncthreads();
    }

    __shared__ __align__(16) __nv_bfloat16 Ws[2][128 * WST];
    __shared__ __align__(16) __nv_bfloat16 Xs[2][32 * XST];

    float c[4][4][4];
    #pragma unroll
    for (int i = 0; i < 4; i++)
        #pragma unroll
        for (int j = 0; j < 4; j++)
            #pragma unroll
            for (int r = 0; r < 4; r++) c[i][j][r] = 0.f;

    const uint32_t wsb = smem_u32(Ws), xsb = smem_u32(Xs);

    auto load_stage = [&](int k0, int buf) {
        uint32_t wd = wsb + buf * (128 * WST * 2);
        uint32_t xd = xsb + buf * (32 * XST * 2);
        #pragma unroll
        for (int t = 0; t < 2; t++) {
            int f = tid + t * 256;
            int r = f >> 2, cc = (f & 3) * 8;
            cp16(wd + (uint32_t)((r * WST + cc) * 2),
                 W + (size_t)(R0 + r) * 256 + k0 + cc);
        }
        #pragma unroll
        for (int t = 0; t < 2; t++) {
            int f = tid + t * 256;
            int kk = f >> 4, p = (f & 15) * 8;
            int gp = P0 + p; if (gp > Mt - 8) gp = Mt - 8;
            cp16(xd + (uint32_t)((kk * XST + p) * 2),
                 X + (size_t)(k0 + kk) * Mt + gp);
        }
    };

    load_stage(0, 0);
    cp_commit();

    for (int s = 0; s < 8; s++) {
        cp_wait_all();
        __syncthreads();
        if (s + 1 < 8) { load_stage((s + 1) * 32, (s + 1) & 1); cp_commit(); }
        const int buf = s & 1;
        const uint32_t wb = wsb + buf * (128 * WST * 2);
        const uint32_t xb = xsb + buf * (32 * XST * 2);

        #pragma unroll
        for (int kk = 0; kk < 2; kk++) {
            uint32_t af[4][4], bf[4][2];
            {
                int rr = ((lane >> 3) & 1) * 8 + (lane & 7);
                int ch = (lane >> 4) & 1;
                #pragma unroll
                for (int rf = 0; rf < 4; rf++)
                    ldm_x4(af[rf], wb + (uint32_t)(((wR + rf * 16 + rr) * WST + kk * 16 + ch * 8) * 2));
            }
            {
                int krow = (lane & 7) + ((lane >> 3) & 1) * 8;
                int pc = ((lane >> 4) & 1) * 8;
                #pragma unroll
                for (int pf = 0; pf < 2; pf++) {
                    uint32_t r4[4];
                    ldm_x4_t(r4, xb + (uint32_t)(((kk * 16 + krow) * XST + wP + pf * 16 + pc) * 2));
                    bf[2 * pf][0] = r4[0]; bf[2 * pf][1] = r4[1];
                    bf[2 * pf + 1][0] = r4[2]; bf[2 * pf + 1][1] = r4[3];
                }
            }
            #pragma unroll
            for (int rf = 0; rf < 4; rf++)
                #pragma unroll
                for (int pg = 0; pg < 4; pg++)
                    mma_bf16(c[rf][pg], af[rf], bf[pg]);
        }
        __syncthreads();
    }

    float a1 = 1.f;
    if (mode == 1) a1 = s_rstd * SCALE_ * LOG2E_;
    #pragma unroll
    for (int rf = 0; rf < 4; rf++) {
        int R = R0 + wR + rf * 16 + (lane >> 2);
        float cv1, cv2;
        if (mode == 1) {
            cv1 = SCALE_ * LOG2E_ * (bq[R]     - s_rstd * s_mu * g_wqsum[R]);
            cv2 = SCALE_ * LOG2E_ * (bq[R + 8] - s_rstd * s_mu * g_wqsum[R + 8]);
        } else {
            const float* cvec = (mode == 0) ? bk : bv;
            cv1 = cvec[R]; cv2 = cvec[R + 8];
        }
        #pragma unroll
        for (int pg = 0; pg < 4; pg++) {
            int P = P0 + wP + pg * 8 + (lane & 3) * 2;
            if (P < Mt) {
                if (mode == 2) {
                    __half* ob = g_v + (size_t)b * 256 * KHW_;
                    *(__half2*)(ob + (size_t)R * KHW_ + P) =
                        __floats2half2_rn(c[rf][pg][0] + cv1, c[rf][pg][1] + cv1);
                    *(__half2*)(ob + (size_t)(R + 8) * KHW_ + P) =
                        __floats2half2_rn(c[rf][pg][2] + cv2, c[rf][pg][3] + cv2);
                } else {
                    __nv_bfloat16* ob = (mode == 1) ? (g_q + (size_t)b * 256 * HW_)
                                                    : (g_k + (size_t)b * 256 * KHW_);
                    *(__nv_bfloat162*)(ob + (size_t)R * Mt + P) =
                        __floats2bfloat162_rn(a1 * c[rf][pg][0] + cv1, a1 * c[rf][pg][1] + cv1);
                    *(__nv_bfloat162*)(ob + (size_t)(R + 8) * Mt + P) =
                        __floats2bfloat162_rn(a1 * c[rf][pg][2] + cv2, a1 * c[rf][pg][3] + cv2);
                }
            }
        }
    }
}

// ---------------------------------------------------------------------------
// O projection mma GEMM (2-stage cp.async) + fused bias + flat residual add
// ---------------------------------------------------------------------------
__global__ void __launch_bounds__(256, 2) gemm_o(
    const __nv_bfloat16* __restrict__ A, const float* __restrict__ bo,
    const float* __restrict__ x, float* __restrict__ out)
{
    __shared__ __align__(16) __nv_bfloat16 As[2][128 * WST];
    __shared__ __align__(16) __nv_bfloat16 Bs[2][128 * WST];
    const int I0 = blockIdx.x * 128;
    const int N0 = blockIdx.y * 128;
    const int b  = blockIdx.z;
    const int tid = threadIdx.x, lane = tid & 31, w = tid >> 5;
    const int wI = (w >> 2) * 64, wN = (w & 3) * 32;

    float c[4][4][4];
    #pragma unroll
    for (int i = 0; i < 4; i++)
        #pragma unroll
        for (int j = 0; j < 4; j++)
            #pragma unroll
            for (int r = 0; r < 4; r++) c[i][j][r] = 0.f;

    const uint32_t asb = smem_u32(As), bsb = smem_u32(Bs);

    auto load_stage = [&](int k0, int buf) {
        uint32_t ad = asb + buf * (128 * WST * 2);
        uint32_t bd = bsb + buf * (128 * WST * 2);
        #pragma unroll
        for (int t = 0; t < 2; t++) {
            int f = tid + t * 256;
            int i = f >> 2, cc = (f & 3) * 8;
            int gi = I0 + i; if (gi > HW_ - 1) gi = HW_ - 1;
            cp16(ad + (uint32_t)((i * WST + cc) * 2),
                 A + ((size_t)(b * HW_) + gi) * 256 + k0 + cc);
        }
        #pragma unroll
        for (int t = 0; t < 2; t++) {
            int f = tid + t * 256;
            int n = f >> 2, cc = (f & 3) * 8;
            cp16(bd + (uint32_t)((n * WST + cc) * 2),
                 g_wo + (size_t)(N0 + n) * 256 + k0 + cc);
        }
    };

    load_stage(0, 0);
    cp_commit();

    for (int s = 0; s < 8; s++) {
        cp_wait_all();
        __syncthreads();
        if (s + 1 < 8) { load_stage((s + 1) * 32, (s + 1) & 1); cp_commit(); }
        const int buf = s & 1;
        const uint32_t ab = asb + buf * (128 * WST * 2);
        const uint32_t bb = bsb + buf * (128 * WST * 2);

        #pragma unroll
        for (int kk = 0; kk < 2; kk++) {
            int rr = ((lane >> 3) & 1) * 8 + (lane & 7);
            int ch = (lane >> 4) & 1;
            uint32_t af[4][4], bf[4][2];
            #pragma unroll
            for (int mf = 0; mf < 4; mf++)
                ldm_x4(af[mf], ab + (uint32_t)(((wI + mf * 16 + rr) * WST + kk * 16 + ch * 8) * 2));
            #pragma unroll
            for (int ng = 0; ng < 2; ng++) {
                uint32_t r4[4];
                ldm_x4(r4, bb + (uint32_t)(((wN + ng * 16 + rr) * WST + kk * 16 + ch * 8) * 2));
                bf[2 * ng][0] = r4[0]; bf[2 * ng][1] = r4[2];
                bf[2 * ng + 1][0] = r4[1]; bf[2 * ng + 1][1] = r4[3];
            }
            #pragma unroll
            for (int mf = 0; mf < 4; mf++)
                #pragma unroll
                for (int nf = 0; nf < 4; nf++)
                    mma_bf16(c[mf][nf], af[mf], bf[nf]);
        }
        __syncthreads();
    }

    #pragma unroll
    for (int mf = 0; mf < 4; mf++) {
        int i1 = I0 + wI + mf * 16 + (lane >> 2);
        int i2 = i1 + 8;
        #pragma unroll
        for (int nf = 0; nf < 4; nf++) {
            int n = N0 + wN + nf * 8 + (lane & 3) * 2;
            float b0v = bo[n], b1v = bo[n + 1];
            if (i1 < HW_) {
                size_t flat = (size_t)b * (256 * HW_) + (size_t)i1 * 256 + n;
                float2 xv = *(const float2*)(x + flat);
                *(float2*)(out + flat) =
                    make_float2(c[mf][nf][0] + b0v + xv.x, c[mf][nf][1] + b1v + xv.y);
            }
            if (i2 < HW_) {
                size_t flat = (size_t)b * (256 * HW_) + (size_t)i2 * 256 + n;
                float2 xv = *(const float2*)(x + flat);
                *(float2*)(out + flat) =
                    make_float2(c[mf][nf][2] + b0v + xv.x, c[mf][nf][3] + b1v + xv.y);
            }
        }
    }
}

// ---------------------------------------------------------------------------
// Flash attention (unchanged from best config): 4 warps x 32 q-rows, K frags
// reused across row groups, log2-domain fixed-max softmax, ones-column mma
// denominators, 2-stage cp.async, 128 threads, 3 blocks/SM.
// ---------------------------------------------------------------------------
#define QST 136
#define KST 72
#define BST 72
#define KBUF (32 * KST * 2)          // 4608
#define BBUF (128 * BST * 2)         // 18432
#define STAGEB (2 * KBUF + BBUF)     // 27648
#define STG0_ 8704
#define ATT_SMEM (STG0_ + 2 * STAGEB)  // 64000

__global__ void __launch_bounds__(128, 3) attn_mma_kernel(
    const __nv_bfloat16* __restrict__ qb, const __nv_bfloat16* __restrict__ kb,
    const __half* __restrict__ vb, const __half* __restrict__ bias,
    __nv_bfloat16* __restrict__ res)
{
    extern __shared__ __align__(16) char smraw[];
    __nv_bfloat16* Qs = (__nv_bfloat16*)smraw;

    const int b = blockIdx.x, h = blockIdx.y;
    const int i0 = blockIdx.z * 128;
    const int tid = threadIdx.x, lane = tid & 31, w = tid >> 5;

    const __nv_bfloat16* qsrc = qb + ((size_t)b * 256 + h * 32) * HW_;
    const __nv_bfloat16* ksrc = kb + ((size_t)b * 256 + h * 32) * KHW_;
    const __half*        vsrc = vb + ((size_t)b * 256 + h * 32) * KHW_;
    const __half*        bias_h = bias + (size_t)h * HW_ * KHW_;

    const uint32_t qbase = smem_u32(smraw);
    const uint32_t stage0 = qbase + STG0_;

    #pragma unroll
    for (int f = tid; f < 512; f += 128) {
        int d = f >> 4, ii = (f & 15) * 8;
        int gi = i0 + ii; if (gi > HW_ - 8) gi = HW_ - 8;
        *(uint4*)&Qs[d * QST + ii] = *(const uint4*)(qsrc + (size_t)d * HW_ + gi);
    }

    auto load_tile = [&](int j0, int buf) {
        uint32_t sb = stage0 + buf * STAGEB;
        #pragma unroll
        for (int t = 0; t < 2; t++) {
            int f = tid + t * 128;
            int d = f >> 3, jj = (f & 7) * 8;
            int gj = j0 + jj; if (gj > KHW_ - 8) gj = KHW_ - 8;
            cp16(sb + (uint32_t)((d * KST + jj) * 2), ksrc + (size_t)d * KHW_ + gj);
            cp16(sb + KBUF + (uint32_t)((d * KST + jj) * 2), vsrc + (size_t)d * KHW_ + gj);
        }
        #pragma unroll
        for (int t = 0; t < 8; t++) {
            int f = tid + t * 128;
            int r = f >> 3, c8 = (f & 7) * 8;
            int gr = i0 + r; if (gr > HW_ - 1) gr = HW_ - 1;
            int gc = j0 + c8; if (gc > KHW_ - 8) gc = KHW_ - 8;
            cp16(sb + 2 * KBUF + (uint32_t)((r * BST + c8) * 2),
                 bias_h + (size_t)gr * KHW_ + gc);
        }
    };

    load_tile(0, 0);
    cp_commit();
    __syncthreads();

    uint32_t qa[2][2][4];
    {
        int krow = (lane & 7) + ((lane >> 4) & 1) * 8;
        #pragma unroll
        for (int g = 0; g < 2; g++) {
            int mcol = w * 32 + g * 16 + ((lane >> 3) & 1) * 8;
            #pragma unroll
            for (int kk = 0; kk < 2; kk++)
                ldm_x4_t(qa[g][kk], qbase + (uint32_t)(((kk * 16 + krow) * QST + mcol) * 2));
        }
    }

    float oacc[2][4][4];
    float c5[2][4];
    #pragma unroll
    for (int g = 0; g < 2; g++) {
        #pragma unroll
        for (int nf = 0; nf < 4; nf++)
            #pragma unroll
            for (int r = 0; r < 4; r++) oacc[g][nf][r] = 0.f;
        #pragma unroll
        for (int r = 0; r < 4; r++) c5[g][r] = 0.f;
    }
    const uint32_t bone = (lane < 4) ? 0x3C003C00u : 0u;
    uint32_t bones[2] = {bone, bone};

    const int rr = ((lane >> 3) & 1) * 8 + (lane & 7);
    const int ch = (lane >> 4) & 1;

    #pragma unroll 1
    for (int jt = 0; jt < 13; jt++) {
        cp_wait_all();
        __syncthreads();
        if (jt + 1 < 13) { load_tile((jt + 1) * 64, (jt + 1) & 1); cp_commit(); }

        const uint32_t sb = stage0 + (jt & 1) * STAGEB;
        const uint32_t kbase = sb;
        const uint32_t vbase = sb + KBUF;
        const uint32_t bbase = sb + 2 * KBUF;

        uint32_t kbf[2][8][2];
        {
            int krow = (lane & 7) + ((lane >> 3) & 1) * 8;
            int ncol = ((lane >> 4) & 1) * 8;
            #pragma unroll
            for (int kk = 0; kk < 2; kk++)
                #pragma unroll
                for (int jg = 0; jg < 4; jg++) {
                    uint32_t r4[4];
                    ldm_x4_t(r4, kbase + (uint32_t)(((kk * 16 + krow) * KST + jg * 16 + ncol) * 2));
                    kbf[kk][2 * jg][0] = r4[0]; kbf[kk][2 * jg][1] = r4[1];
                    kbf[kk][2 * jg + 1][0] = r4[2]; kbf[kk][2 * jg + 1][1] = r4[3];
                }
        }

        #pragma unroll
        for (int g = 0; g < 2; g++) {
            float s[8][4];
            #pragma unroll
            for (int nf = 0; nf < 8; nf++)
                #pragma unroll
                for (int r = 0; r < 4; r++) s[nf][r] = 0.f;
            #pragma unroll
            for (int kk = 0; kk < 2; kk++)
                #pragma unroll
                for (int nf = 0; nf < 8; nf++)
                    mma_bf16(s[nf], qa[g][kk], kbf[kk][nf]);

            const int brow = w * 32 + g * 16 + rr;
            uint32_t pa[4][4];
            if (jt < 12) {
                #pragma unroll
                for (int cg = 0; cg < 4; cg++) {
                    uint32_t bb4[4];
                    ldm_x4(bb4, bbase + (uint32_t)((brow * BST + cg * 16 + ch * 8) * 2));
                    pa[cg][0] = bias_ex2(s[2 * cg][0],     s[2 * cg][1],     bb4[0]);
                    pa[cg][1] = bias_ex2(s[2 * cg][2],     s[2 * cg][3],     bb4[1]);
                    pa[cg][2] = bias_ex2(s[2 * cg + 1][0], s[2 * cg + 1][1], bb4[2]);
                    pa[cg][3] = bias_ex2(s[2 * cg + 1][2], s[2 * cg + 1][3], bb4[3]);
                }
            } else {
                uint32_t bb4[4];
                ldm_x4(bb4, bbase + (uint32_t)((brow * BST + ch * 8) * 2));
                pa[0][0] = bias_ex2(s[0][0], s[0][1], bb4[0]);
                pa[0][1] = bias_ex2(s[0][2], s[0][3], bb4[1]);
                pa[0][2] = bias_ex2(s[1][0], s[1][1], bb4[2]);
                pa[0][3] = bias_ex2(s[1][2], s[1][3], bb4[3]);
                #pragma unroll
                for (int cg = 1; cg < 4; cg++)
                    #pragma unroll
                    for (int r = 0; r < 4; r++) pa[cg][r] = 0u;
            }

            #pragma unroll
            for (int kf = 0; kf < 4; kf++) {
                uint32_t vk[4][2];
                #pragma unroll
                for (int ng = 0; ng < 2; ng++) {
                    uint32_t r4[4];
                    ldm_x4(r4, vbase + (uint32_t)(((ng * 16 + rr) * KST + kf * 16 + ch * 8) * 2));
                    vk[2 * ng][0] = r4[0]; vk[2 * ng][1] = r4[2];
                    vk[2 * ng + 1][0] = r4[1]; vk[2 * ng + 1][1] = r4[3];
                }
                #pragma unroll
                for (int nf = 0; nf < 4; nf++)
                    mma_f16(oacc[g][nf], pa[kf], vk[nf]);
                mma_f16(c5[g], pa[kf], bones);
            }
        }
    }

    int src = (lane >> 2) << 2;
    #pragma unroll
    for (int g = 0; g < 2; g++) {
        float l0 = __shfl_sync(0xffffffffu, c5[g][0], src);
        float l1 = __shfl_sync(0xffffffffu, c5[g][2], src);
        float inv0 = 1.f / l0, inv1 = 1.f / l1;
        int giA = i0 + w * 32 + g * 16 + (lane >> 2);
        int giB = giA + 8;
        #pragma unroll
        for (int nf = 0; nf < 4; nf++) {
            int col = h * 32 + nf * 8 + (lane & 3) * 2;
            if (giA < HW_)
                *(__nv_bfloat162*)(res + ((size_t)(b * HW_ + giA)) * 256 + col) =
                    __floats2bfloat162_rn(oacc[g][nf][0] * inv0, oacc[g][nf][1] * inv0);
            if (giB < HW_)
                *(__nv_bfloat162*)(res + ((size_t)(b * HW_ + giB)) * 256 + col) =
                    __floats2bfloat162_rn(oacc[g][nf][2] * inv1, oacc[g][nf][3] * inv1);
        }
    }
}

// ---------------------------------------------------------------------------
extern "C" void kernel_launch(void* const* d_in, const int* in_sizes, int n_in,
                              void* d_out, int out_size) {
    const float* x     = (const float*)d_in[0];
    const float* Wk_dw = (const float*)d_in[1];
    const float* bk_dw = (const float*)d_in[2];
    const float* Wv_dw = (const float*)d_in[3];
    const float* bv_dw = (const float*)d_in[4];
    const float* Wq    = (const float*)d_in[5];
    const float* bq    = (const float*)d_in[6];
    const float* Wk    = (const float*)d_in[7];
    const float* bk    = (const float*)d_in[8];
    const float* Wv    = (const float*)d_in[9];
    const float* bv    = (const float*)d_in[10];
    const float* Wo    = (const float*)d_in[11];
    const float* bo    = (const float*)d_in[12];
    const float* Bb    = (const float*)d_in[13];
    float* out = (float*)d_out;

    __nv_bfloat16 *qp, *kp, *resp;
    __half *vp, *bbfp;
    cudaGetSymbolAddress((void**)&qp,   g_q);
    cudaGetSymbolAddress((void**)&kp,   g_k);
    cudaGetSymbolAddress((void**)&vp,   g_v);
    cudaGetSymbolAddress((void**)&resp, g_res);
    cudaGetSymbolAddress((void**)&bbfp, g_bbf);

    cudaFuncSetAttribute(attn_mma_kernel,
                         cudaFuncAttributeMaxDynamicSharedMemorySize, ATT_SMEM);

    cudaStream_t s2;
    cudaStreamCreateWithFlags(&s2, cudaStreamNonBlocking);
    cudaEvent_t evRoot, ev2;
    cudaEventCreateWithFlags(&evRoot, cudaEventDisableTiming);
    cudaEventCreateWithFlags(&ev2,    cudaEventDisableTiming);

    cudaEventRecord(evRoot, 0);
    cudaStreamWaitEvent(s2, evRoot, 0);

    // launch #1: dwconv (side stream, overlaps prep)
    dwconv_kernel<<<(B_ * C_ * KHW_ + 255) / 256, 256, 0, s2>>>(x, Wk_dw, bk_dw, Wv_dw, bv_dw);
    cudaEventRecord(ev2, s2);

    // launch #2: mega-prep (x, weights, bias conversions + LN partials)
    prep_kernel<<<NPART_ + 256 + NBIASBLK_, 256>>>(x, Wq, Wk, Wv, Wo, Bb);

    // launch #3: fused Q+K+V projection (waits on dwconv)
    cudaStreamWaitEvent(0, ev2, 0);
    gemm_qkv<<<dim3(25, 2, 24), 256>>>(bq, bk, bv);

    // launch #4: attention (now at the ncu-profiled position)
    attn_mma_kernel<<<dim3(B_, HEADS_, 25), 128, ATT_SMEM>>>(qp, kp, vp, bbfp, resp);

    // launch #5: O projection + residual
    gemm_o<<<dim3(25, 2, B_), 256>>>(resp, bo, x, out);

    cudaEventDestroy(evRoot);
    cudaEventDestroy(ev2);
    cudaStreamDestroy(s2);
}

// round 15
// speedup vs baseline: 1.1383x; 1.1383x over previous
#include <cuda_runtime.h>
#include <cuda_bf16.h>
#include <cuda_fp16.h>
#include <math.h>
#include <stdint.h>

// Problem constants
#define B_   8
#define C_   256
#define H_   56
#define W_   56
#define HW_  3136        // 56*56
#define KHW_ 784         // 28*28
#define HEADS_ 8
#define NTOT_ 6422528    // B*C*HW
#define NPART_ 6272
#define BIASN_ 19668992  // HEADS*HW*KHW
#define EPS_ 1e-5
#define SCALE_ 0.17677669529663687f   // 1/sqrt(32)
#define LOG2E_ 1.4426950408889634f

// Scratch (static device arrays — allocation-free)
__device__ __nv_bfloat16 g_q[B_ * 256 * HW_];    // [b][hd][i]  (log2e-scaled)
__device__ __nv_bfloat16 g_k[B_ * 256 * KHW_];   // [b][hd][j]
__device__ __half        g_v[B_ * 256 * KHW_];   // [b][hd][j]  fp16
__device__ __nv_bfloat16 g_res[B_ * HW_ * 256];  // [b][i][hd]
__device__ __nv_bfloat16 g_ck[B_ * C_ * KHW_];
__device__ __nv_bfloat16 g_cv[B_ * C_ * KHW_];
__device__ __nv_bfloat16 g_xbf[NTOT_];
__device__ __half        g_bbf[BIASN_];          // bias*log2e in fp16
__device__ __nv_bfloat16 g_wq[65536], g_wk[65536], g_wv[65536], g_wo[65536];
__device__ float g_part[2 * NPART_];
__device__ float g_wqsum[256];
__device__ float g_stats[2];
__device__ float g_cq[256];

// ---------------------------------------------------------------------------
// asm helpers
// ---------------------------------------------------------------------------
__device__ __forceinline__ uint32_t smem_u32(const void* p) {
    return (uint32_t)__cvta_generic_to_shared(p);
}
__device__ __forceinline__ void ldm_x4(uint32_t* r, uint32_t addr) {
    asm volatile("ldmatrix.sync.aligned.m8n8.x4.shared.b16 {%0,%1,%2,%3}, [%4];"
        : "=r"(r[0]), "=r"(r[1]), "=r"(r[2]), "=r"(r[3]) : "r"(addr));
}
__device__ __forceinline__ void ldm_x4_t(uint32_t* r, uint32_t addr) {
    asm volatile("ldmatrix.sync.aligned.m8n8.x4.trans.shared.b16 {%0,%1,%2,%3}, [%4];"
        : "=r"(r[0]), "=r"(r[1]), "=r"(r[2]), "=r"(r[3]) : "r"(addr));
}
__device__ __forceinline__ void mma_bf16(float* d, const uint32_t* a, const uint32_t* b) {
    asm volatile(
        "mma.sync.aligned.m16n8k16.row.col.f32.bf16.bf16.f32 "
        "{%0,%1,%2,%3}, {%4,%5,%6,%7}, {%8,%9}, {%0,%1,%2,%3};"
        : "+f"(d[0]), "+f"(d[1]), "+f"(d[2]), "+f"(d[3])
        : "r"(a[0]), "r"(a[1]), "r"(a[2]), "r"(a[3]), "r"(b[0]), "r"(b[1]));
}
__device__ __forceinline__ void mma_f16(float* d, const uint32_t* a, const uint32_t* b) {
    asm volatile(
        "mma.sync.aligned.m16n8k16.row.col.f32.f16.f16.f32 "
        "{%0,%1,%2,%3}, {%4,%5,%6,%7}, {%8,%9}, {%0,%1,%2,%3};"
        : "+f"(d[0]), "+f"(d[1]), "+f"(d[2]), "+f"(d[3])
        : "r"(a[0]), "r"(a[1]), "r"(a[2]), "r"(a[3]), "r"(b[0]), "r"(b[1]));
}
__device__ __forceinline__ uint32_t bias_ex2(float lo, float hi, uint32_t bias2) {
    uint32_t t, u, r;
    asm("cvt.rn.f16x2.f32 %0, %1, %2;" : "=r"(t) : "f"(hi), "f"(lo));
    asm("add.f16x2 %0, %1, %2;" : "=r"(u) : "r"(t), "r"(bias2));
    asm("ex2.approx.f16x2 %0, %1;" : "=r"(r) : "r"(u));
    return r;
}
__device__ __forceinline__ void cp16(uint32_t dst, const void* src) {
    asm volatile("cp.async.cg.shared.global [%0], [%1], 16;" :: "r"(dst), "l"(src));
}
__device__ __forceinline__ void cp_commit() {
    asm volatile("cp.async.commit_group;" ::: "memory");
}
__device__ __forceinline__ void cp_wait_all() {
    asm volatile("cp.async.wait_group 0;" ::: "memory");
}

// ---------------------------------------------------------------------------
// Fused: x fp32 -> bf16 + LN partial sums
// ---------------------------------------------------------------------------
__global__ void cvt_x_stats(const float* __restrict__ x) {
    int tid = threadIdx.x;
    int i = blockIdx.x * 256 + tid;
    float4 v = ((const float4*)x)[i];
    __nv_bfloat162* o = (__nv_bfloat162*)(g_xbf + (size_t)i * 4);
    o[0] = __floats2bfloat162_rn(v.x, v.y);
    o[1] = __floats2bfloat162_rn(v.z, v.w);
    float s  = v.x + v.y + v.z + v.w;
    float ss = v.x * v.x + v.y * v.y + v.z * v.z + v.w * v.w;
    #pragma unroll
    for (int ofs = 16; ofs; ofs >>= 1) {
        s  += __shfl_xor_sync(0xffffffffu, s, ofs);
        ss += __shfl_xor_sync(0xffffffffu, ss, ofs);
    }
    __shared__ float sh[16];
    int w = tid >> 5, lane = tid & 31;
    if (lane == 0) { sh[w] = s; sh[8 + w] = ss; }
    __syncthreads();
    if (tid == 0) {
        float a = 0.f, b = 0.f;
        #pragma unroll
        for (int k = 0; k < 8; k++) { a += sh[k]; b += sh[8 + k]; }
        g_part[blockIdx.x] = a;
        g_part[NPART_ + blockIdx.x] = b;
    }
}

// ---------------------------------------------------------------------------
// Weight conversions (vectorized) + Wq rowsum
// ---------------------------------------------------------------------------
__global__ void cvt_w_kernel(const float* __restrict__ Wq, const float* __restrict__ Wk,
                             const float* __restrict__ Wv, const float* __restrict__ Wo) {
    int r = blockIdx.x, tid = threadIdx.x;
    int base = r * 256 + (tid & 63) * 4;
    int grp = tid >> 6;
    const float* src = (grp == 0) ? Wq : (grp == 1) ? Wk : (grp == 2) ? Wv : Wo;
    __nv_bfloat16* dst = (grp == 0) ? g_wq : (grp == 1) ? g_wk : (grp == 2) ? g_wv : g_wo;
    float4 v = *(const float4*)(src + base);
    *(__nv_bfloat162*)(dst + base)     = __floats2bfloat162_rn(v.x, v.y);
    *(__nv_bfloat162*)(dst + base + 2) = __floats2bfloat162_rn(v.z, v.w);
    float s = (grp == 0) ? (v.x + v.y) + (v.z + v.w) : 0.f;
    #pragma unroll
    for (int ofs = 16; ofs; ofs >>= 1) s += __shfl_xor_sync(0xffffffffu, s, ofs);
    __shared__ float sh[8];
    if ((tid & 31) == 0) sh[tid >> 5] = s;
    __syncthreads();
    if (tid == 0) g_wqsum[r] = sh[0] + sh[1];
}

// ---------------------------------------------------------------------------
// Bias fp32 -> fp16 * log2e
// ---------------------------------------------------------------------------
__global__ void cvt_bias(const float* __restrict__ Bb) {
    size_t i = (size_t)blockIdx.x * 256 + threadIdx.x;
    float4 a = ((const float4*)Bb)[2 * i];
    float4 b = ((const float4*)Bb)[2 * i + 1];
    __half2* o = (__half2*)(g_bbf + i * 8);
    o[0] = __floats2half2_rn(a.x * LOG2E_, a.y * LOG2E_);
    o[1] = __floats2half2_rn(a.z * LOG2E_, a.w * LOG2E_);
    o[2] = __floats2half2_rn(b.x * LOG2E_, b.y * LOG2E_);
    o[3] = __floats2half2_rn(b.z * LOG2E_, b.w * LOG2E_);
}

// ---------------------------------------------------------------------------
// Finalize mu/rstd + folded Q bias
// ---------------------------------------------------------------------------
__global__ void stats_final(const float* __restrict__ bq) {
    int tid = threadIdx.x;
    const float4* p4  = (const float4*)g_part;
    const float4* ps4 = (const float4*)(g_part + NPART_);
    double s = 0.0, ss = 0.0;
    for (int i = tid; i < NPART_ / 4; i += 256) {
        float4 a = p4[i];
        float4 b = ps4[i];
        s  += (double)((a.x + a.y) + (a.z + a.w));
        ss += (double)((b.x + b.y) + (b.z + b.w));
    }
    __shared__ double shs[256], shss[256];
    shs[tid] = s; shss[tid] = ss;
    __syncthreads();
    for (int o = 128; o; o >>= 1) {
        if (tid < o) { shs[tid] += shs[tid + o]; shss[tid] += shss[tid + o]; }
        __syncthreads();
    }
    __shared__ float mu_s, rstd_s;
    if (tid == 0) {
        double N = (double)NTOT_;
        double mu = shs[0] / N;
        double var = shss[0] / N - mu * mu;
        float rstd = (float)(1.0 / sqrt(var + EPS_));
        g_stats[0] = (float)mu;
        g_stats[1] = rstd;
        mu_s = (float)mu; rstd_s = rstd;
    }
    __syncthreads();
    g_cq[tid] = bq[tid] - rstd_s * mu_s * g_wqsum[tid];
}

// ---------------------------------------------------------------------------
// Depthwise 3x3 stride-2 conv (K and V paths fused), bf16 output
// ---------------------------------------------------------------------------
__global__ void dwconv_kernel(const float* __restrict__ x,
                              const float* __restrict__ wk, const float* __restrict__ bkd,
                              const float* __restrict__ wv, const float* __restrict__ bvd) {
    int idx = blockIdx.x * blockDim.x + threadIdx.x;
    if (idx >= B_ * C_ * KHW_) return;
    int ox = idx % 28;
    int oy = (idx / 28) % 28;
    int c  = (idx / KHW_) % C_;
    int b  = idx / (KHW_ * C_);
    const float* xp = x + ((size_t)(b * C_ + c)) * HW_;
    float ak = 0.f, av = 0.f;
    #pragma unroll
    for (int ky = 0; ky < 3; ky++) {
        int iy = oy * 2 + ky - 1;
        if (iy < 0 || iy >= H_) continue;
        #pragma unroll
        for (int kx = 0; kx < 3; kx++) {
            int ix = ox * 2 + kx - 1;
            if (ix < 0 || ix >= W_) continue;
            float xv = xp[iy * W_ + ix];
            ak += xv * wk[c * 9 + ky * 3 + kx];
            av += xv * wv[c * 9 + ky * 3 + kx];
        }
    }
    g_ck[idx] = __float2bfloat16(ak + bkd[c]);
    g_cv[idx] = __float2bfloat16(av + bvd[c]);
}

// ---------------------------------------------------------------------------
// bf16 mma GEMM (2-stage cp.async): Q projection (mode 1)
// ---------------------------------------------------------------------------
#define WST 40
#define XST 136
__global__ void __launch_bounds__(256, 2) gemm_wx(
    const __nv_bfloat16* __restrict__ W, const __nv_bfloat16* __restrict__ X,
    const float* __restrict__ cvec, int mode, int Mt,
    void* __restrict__ outp)
{
    __shared__ __align__(16) __nv_bfloat16 Ws[2][128 * WST];
    __shared__ __align__(16) __nv_bfloat16 Xs[2][32 * XST];
    const int P0 = blockIdx.x * 128;
    const int R0 = blockIdx.y * 128;
    const int b  = blockIdx.z;
    const __nv_bfloat16* Xb = X + (size_t)b * 256 * Mt;
    const int tid = threadIdx.x, lane = tid & 31, w = tid >> 5;
    const int wR = (w >> 2) * 64, wP = (w & 3) * 32;

    float c[4][4][4];
    #pragma unroll
    for (int i = 0; i < 4; i++)
        #pragma unroll
        for (int j = 0; j < 4; j++)
            #pragma unroll
            for (int r = 0; r < 4; r++) c[i][j][r] = 0.f;

    const uint32_t wsb = smem_u32(Ws), xsb = smem_u32(Xs);

    auto load_stage = [&](int k0, int buf) {
        uint32_t wd = wsb + buf * (128 * WST * 2);
        uint32_t xd = xsb + buf * (32 * XST * 2);
        #pragma unroll
        for (int t = 0; t < 2; t++) {
            int f = tid + t * 256;
            int r = f >> 2, cc = (f & 3) * 8;
            cp16(wd + (uint32_t)((r * WST + cc) * 2),
                 W + (size_t)(R0 + r) * 256 + k0 + cc);
        }
        #pragma unroll
        for (int t = 0; t < 2; t++) {
            int f = tid + t * 256;
            int kk = f >> 4, p = (f & 15) * 8;
            int gp = P0 + p; if (gp > Mt - 8) gp = Mt - 8;
            cp16(xd + (uint32_t)((kk * XST + p) * 2),
                 Xb + (size_t)(k0 + kk) * Mt + gp);
        }
    };

    load_stage(0, 0);
    cp_commit();

    for (int s = 0; s < 8; s++) {
        cp_wait_all();
        __syncthreads();
        if (s + 1 < 8) { load_stage((s + 1) * 32, (s + 1) & 1); cp_commit(); }
        const int buf = s & 1;
        const uint32_t wb = wsb + buf * (128 * WST * 2);
        const uint32_t xb = xsb + buf * (32 * XST * 2);

        #pragma unroll
        for (int kk = 0; kk < 2; kk++) {
            uint32_t af[4][4], bf[4][2];
            {
                int rr = ((lane >> 3) & 1) * 8 + (lane & 7);
                int ch = (lane >> 4) & 1;
                #pragma unroll
                for (int rf = 0; rf < 4; rf++)
                    ldm_x4(af[rf], wb + (uint32_t)(((wR + rf * 16 + rr) * WST + kk * 16 + ch * 8) * 2));
            }
            {
                int krow = (lane & 7) + ((lane >> 3) & 1) * 8;
                int pc = ((lane >> 4) & 1) * 8;
                #pragma unroll
                for (int pf = 0; pf < 2; pf++) {
                    uint32_t r4[4];
                    ldm_x4_t(r4, xb + (uint32_t)(((kk * 16 + krow) * XST + wP + pf * 16 + pc) * 2));
                    bf[2 * pf][0] = r4[0]; bf[2 * pf][1] = r4[1];
                    bf[2 * pf + 1][0] = r4[2]; bf[2 * pf + 1][1] = r4[3];
                }
            }
            #pragma unroll
            for (int rf = 0; rf < 4; rf++)
                #pragma unroll
                for (int pg = 0; pg < 4; pg++)
                    mma_bf16(c[rf][pg], af[rf], bf[pg]);
        }
        __syncthreads();
    }

    float a1 = 1.f, a2 = 1.f;
    if (mode == 1) { a1 = g_stats[1] * SCALE_ * LOG2E_; a2 = SCALE_ * LOG2E_; }
    #pragma unroll
    for (int rf = 0; rf < 4; rf++) {
        int R = R0 + wR + rf * 16 + (lane >> 2);
        float cv1 = a2 * cvec[R], cv2 = a2 * cvec[R + 8];
        #pragma unroll
        for (int pg = 0; pg < 4; pg++) {
            int P = P0 + wP + pg * 8 + (lane & 3) * 2;
            if (P < Mt) {
                __nv_bfloat16* ob = (__nv_bfloat16*)outp + (size_t)b * 256 * Mt;
                *(__nv_bfloat162*)(ob + (size_t)R * Mt + P) =
                    __floats2bfloat162_rn(a1 * c[rf][pg][0] + cv1, a1 * c[rf][pg][1] + cv1);
                *(__nv_bfloat162*)(ob + (size_t)(R + 8) * Mt + P) =
                    __floats2bfloat162_rn(a1 * c[rf][pg][2] + cv2, a1 * c[rf][pg][3] + cv2);
            }
        }
    }
}

// Fused K+V projection: blockIdx.z = b*2 + isV.
__global__ void __launch_bounds__(256, 2) gemm_kv(
    const float* __restrict__ bk, const float* __restrict__ bv)
{
    const int z = blockIdx.z;
    const int b = z >> 1, isV = z & 1;
    const __nv_bfloat16* W = isV ? g_wv : g_wk;
    const __nv_bfloat16* X = (isV ? g_cv : g_ck) + (size_t)b * 256 * KHW_;
    const float* cvec = isV ? bv : bk;

    __shared__ __align__(16) __nv_bfloat16 Ws[2][128 * WST];
    __shared__ __align__(16) __nv_bfloat16 Xs[2][32 * XST];
    const int P0 = blockIdx.x * 128;
    const int R0 = blockIdx.y * 128;
    const int tid = threadIdx.x, lane = tid & 31, w = tid >> 5;
    const int wR = (w >> 2) * 64, wP = (w & 3) * 32;

    float c[4][4][4];
    #pragma unroll
    for (int i = 0; i < 4; i++)
        #pragma unroll
        for (int j = 0; j < 4; j++)
            #pragma unroll
            for (int r = 0; r < 4; r++) c[i][j][r] = 0.f;

    const uint32_t wsb = smem_u32(Ws), xsb = smem_u32(Xs);

    auto load_stage = [&](int k0, int buf) {
        uint32_t wd = wsb + buf * (128 * WST * 2);
        uint32_t xd = xsb + buf * (32 * XST * 2);
        #pragma unroll
        for (int t = 0; t < 2; t++) {
            int f = tid + t * 256;
            int r = f >> 2, cc = (f & 3) * 8;
            cp16(wd + (uint32_t)((r * WST + cc) * 2),
                 W + (size_t)(R0 + r) * 256 + k0 + cc);
        }
        #pragma unroll
        for (int t = 0; t < 2; t++) {
            int f = tid + t * 256;
            int kk = f >> 4, p = (f & 15) * 8;
            int gp = P0 + p; if (gp > KHW_ - 8) gp = KHW_ - 8;
            cp16(xd + (uint32_t)((kk * XST + p) * 2),
                 X + (size_t)(k0 + kk) * KHW_ + gp);
        }
    };

    load_stage(0, 0);
    cp_commit();

    for (int s = 0; s < 8; s++) {
        cp_wait_all();
        __syncthreads();
        if (s + 1 < 8) { load_stage((s + 1) * 32, (s + 1) & 1); cp_commit(); }
        const int buf = s & 1;
        const uint32_t wb = wsb + buf * (128 * WST * 2);
        const uint32_t xb = xsb + buf * (32 * XST * 2);

        #pragma unroll
        for (int kk = 0; kk < 2; kk++) {
            uint32_t af[4][4], bf[4][2];
            {
                int rr = ((lane >> 3) & 1) * 8 + (lane & 7);
                int ch = (lane >> 4) & 1;
                #pragma unroll
                for (int rf = 0; rf < 4; rf++)
                    ldm_x4(af[rf], wb + (uint32_t)(((wR + rf * 16 + rr) * WST + kk * 16 + ch * 8) * 2));
            }
            {
                int krow = (lane & 7) + ((lane >> 3) & 1) * 8;
                int pc = ((lane >> 4) & 1) * 8;
                #pragma unroll
                for (int pf = 0; pf < 2; pf++) {
                    uint32_t r4[4];
                    ldm_x4_t(r4, xb + (uint32_t)(((kk * 16 + krow) * XST + wP + pf * 16 + pc) * 2));
                    bf[2 * pf][0] = r4[0]; bf[2 * pf][1] = r4[1];
                    bf[2 * pf + 1][0] = r4[2]; bf[2 * pf + 1][1] = r4[3];
                }
            }
            #pragma unroll
            for (int rf = 0; rf < 4; rf++)
                #pragma unroll
                for (int pg = 0; pg < 4; pg++)
                    mma_bf16(c[rf][pg], af[rf], bf[pg]);
        }
        __syncthreads();
    }

    #pragma unroll
    for (int rf = 0; rf < 4; rf++) {
        int R = R0 + wR + rf * 16 + (lane >> 2);
        float cv1 = cvec[R], cv2 = cvec[R + 8];
        #pragma unroll
        for (int pg = 0; pg < 4; pg++) {
            int P = P0 + wP + pg * 8 + (lane & 3) * 2;
            if (P < KHW_) {
                if (isV) {
                    __half* ob = g_v + (size_t)b * 256 * KHW_;
                    *(__half2*)(ob + (size_t)R * KHW_ + P) =
                        __floats2half2_rn(c[rf][pg][0] + cv1, c[rf][pg][1] + cv1);
                    *(__half2*)(ob + (size_t)(R + 8) * KHW_ + P) =
                        __floats2half2_rn(c[rf][pg][2] + cv2, c[rf][pg][3] + cv2);
                } else {
                    __nv_bfloat16* ob = g_k + (size_t)b * 256 * KHW_;
                    *(__nv_bfloat162*)(ob + (size_t)R * KHW_ + P) =
                        __floats2bfloat162_rn(c[rf][pg][0] + cv1, c[rf][pg][1] + cv1);
                    *(__nv_bfloat162*)(ob + (size_t)(R + 8) * KHW_ + P) =
                        __floats2bfloat162_rn(c[rf][pg][2] + cv2, c[rf][pg][3] + cv2);
                }
            }
        }
    }
}

// ---------------------------------------------------------------------------
// O projection mma GEMM (2-stage cp.async) + fused bias + flat residual add
// ---------------------------------------------------------------------------
__global__ void __launch_bounds__(256, 2) gemm_o(
    const __nv_bfloat16* __restrict__ A, const __nv_bfloat16* __restrict__ Wo,
    const float* __restrict__ bo, const float* __restrict__ x,
    float* __restrict__ out)
{
    __shared__ __align__(16) __nv_bfloat16 As[2][128 * WST];
    __shared__ __align__(16) __nv_bfloat16 Bs[2][128 * WST];
    const int I0 = blockIdx.x * 128;
    const int N0 = blockIdx.y * 128;
    const int b  = blockIdx.z;
    const int tid = threadIdx.x, lane = tid & 31, w = tid >> 5;
    const int wI = (w >> 2) * 64, wN = (w & 3) * 32;

    float c[4][4][4];
    #pragma unroll
    for (int i = 0; i < 4; i++)
        #pragma unroll
        for (int j = 0; j < 4; j++)
            #pragma unroll
            for (int r = 0; r < 4; r++) c[i][j][r] = 0.f;

    const uint32_t asb = smem_u32(As), bsb = smem_u32(Bs);

    auto load_stage = [&](int k0, int buf) {
        uint32_t ad = asb + buf * (128 * WST * 2);
        uint32_t bd = bsb + buf * (128 * WST * 2);
        #pragma unroll
        for (int t = 0; t < 2; t++) {
            int f = tid + t * 256;
            int i = f >> 2, cc = (f & 3) * 8;
            int gi = I0 + i; if (gi > HW_ - 1) gi = HW_ - 1;
            cp16(ad + (uint32_t)((i * WST + cc) * 2),
                 A + ((size_t)(b * HW_) + gi) * 256 + k0 + cc);
        }
        #pragma unroll
        for (int t = 0; t < 2; t++) {
            int f = tid + t * 256;
            int n = f >> 2, cc = (f & 3) * 8;
            cp16(bd + (uint32_t)((n * WST + cc) * 2),
                 Wo + (size_t)(N0 + n) * 256 + k0 + cc);
        }
    };

    load_stage(0, 0);
    cp_commit();

    for (int s = 0; s < 8; s++) {
        cp_wait_all();
        __syncthreads();
        if (s + 1 < 8) { load_stage((s + 1) * 32, (s + 1) & 1); cp_commit(); }
        const int buf = s & 1;
        const uint32_t ab = asb + buf * (128 * WST * 2);
        const uint32_t bb = bsb + buf * (128 * WST * 2);

        #pragma unroll
        for (int kk = 0; kk < 2; kk++) {
            int rr = ((lane >> 3) & 1) * 8 + (lane & 7);
            int ch = (lane >> 4) & 1;
            uint32_t af[4][4], bf[4][2];
            #pragma unroll
            for (int mf = 0; mf < 4; mf++)
                ldm_x4(af[mf], ab + (uint32_t)(((wI + mf * 16 + rr) * WST + kk * 16 + ch * 8) * 2));
            #pragma unroll
            for (int ng = 0; ng < 2; ng++) {
                uint32_t r4[4];
                ldm_x4(r4, bb + (uint32_t)(((wN + ng * 16 + rr) * WST + kk * 16 + ch * 8) * 2));
                bf[2 * ng][0] = r4[0]; bf[2 * ng][1] = r4[2];
                bf[2 * ng + 1][0] = r4[1]; bf[2 * ng + 1][1] = r4[3];
            }
            #pragma unroll
            for (int mf = 0; mf < 4; mf++)
                #pragma unroll
                for (int nf = 0; nf < 4; nf++)
                    mma_bf16(c[mf][nf], af[mf], bf[nf]);
        }
        __syncthreads();
    }

    #pragma unroll
    for (int mf = 0; mf < 4; mf++) {
        int i1 = I0 + wI + mf * 16 + (lane >> 2);
        int i2 = i1 + 8;
        #pragma unroll
        for (int nf = 0; nf < 4; nf++) {
            int n = N0 + wN + nf * 8 + (lane & 3) * 2;
            float b0v = bo[n], b1v = bo[n + 1];
            if (i1 < HW_) {
                size_t flat = (size_t)b * (256 * HW_) + (size_t)i1 * 256 + n;
                float2 xv = *(const float2*)(x + flat);
                *(float2*)(out + flat) =
                    make_float2(c[mf][nf][0] + b0v + xv.x, c[mf][nf][1] + b1v + xv.y);
            }
            if (i2 < HW_) {
                size_t flat = (size_t)b * (256 * HW_) + (size_t)i2 * 256 + n;
                float2 xv = *(const float2*)(x + flat);
                *(float2*)(out + flat) =
                    make_float2(c[mf][nf][2] + b0v + xv.x, c[mf][nf][3] + b1v + xv.y);
            }
        }
    }
}

// ---------------------------------------------------------------------------
// Flash attention, OCCUPANCY-OPTIMIZED: 4 blocks/SM (16 warps).
// 4 warps x 32 q-rows (two 16-row groups). Q staged temporarily in stage
// buffer 0, fragments extracted, region recycled for the K/V/bias pipeline.
// smem = 2 x 27648 = 55296 B; launch_bounds(128,4) -> <=128 regs.
// K fragments reloaded per kk inside each group (keeps reg peak under 128).
// ---------------------------------------------------------------------------
#define QST 136
#define KST 72
#define BST 72
#define KBUF (32 * KST * 2)          // 4608
#define BBUF (128 * BST * 2)         // 18432
#define STAGEB (2 * KBUF + BBUF)     // 27648
#define ATT_SMEM (2 * STAGEB)        // 55296

__global__ void __launch_bounds__(128, 4) attn_mma_kernel(
    const __nv_bfloat16* __restrict__ qb, const __nv_bfloat16* __restrict__ kb,
    const __half* __restrict__ vb, const __half* __restrict__ bias,
    __nv_bfloat16* __restrict__ res)
{
    extern __shared__ __align__(16) char smraw[];
    __nv_bfloat16* Qs = (__nv_bfloat16*)smraw;    // temporary, recycled

    const int b = blockIdx.x, h = blockIdx.y;
    const int i0 = blockIdx.z * 128;
    const int tid = threadIdx.x, lane = tid & 31, w = tid >> 5;

    const __nv_bfloat16* qsrc = qb + ((size_t)b * 256 + h * 32) * HW_;
    const __nv_bfloat16* ksrc = kb + ((size_t)b * 256 + h * 32) * KHW_;
    const __half*        vsrc = vb + ((size_t)b * 256 + h * 32) * KHW_;
    const __half*        bias_h = bias + (size_t)h * HW_ * KHW_;

    const uint32_t sbase = smem_u32(smraw);

    // --- Stage Q temporarily at smem offset 0, extract fragments, recycle ---
    #pragma unroll
    for (int f = tid; f < 512; f += 128) {
        int d = f >> 4, ii = (f & 15) * 8;
        int gi = i0 + ii; if (gi > HW_ - 8) gi = HW_ - 8;
        *(uint4*)&Qs[d * QST + ii] = *(const uint4*)(qsrc + (size_t)d * HW_ + gi);
    }
    __syncthreads();

    uint32_t qa[2][2][4];
    {
        int krow = (lane & 7) + ((lane >> 4) & 1) * 8;
        #pragma unroll
        for (int g = 0; g < 2; g++) {
            int mcol = w * 32 + g * 16 + ((lane >> 3) & 1) * 8;
            #pragma unroll
            for (int kk = 0; kk < 2; kk++)
                ldm_x4_t(qa[g][kk], sbase + (uint32_t)(((kk * 16 + krow) * QST + mcol) * 2));
        }
    }
    __syncthreads();   // all warps done reading Q; region now reusable

    auto load_tile = [&](int j0, int buf) {
        uint32_t sb = sbase + buf * STAGEB;
        #pragma unroll
        for (int t = 0; t < 2; t++) {
            int f = tid + t * 128;
            int d = f >> 3, jj = (f & 7) * 8;
            int gj = j0 + jj; if (gj > KHW_ - 8) gj = KHW_ - 8;
            cp16(sb + (uint32_t)((d * KST + jj) * 2), ksrc + (size_t)d * KHW_ + gj);
            cp16(sb + KBUF + (uint32_t)((d * KST + jj) * 2), vsrc + (size_t)d * KHW_ + gj);
        }
        #pragma unroll
        for (int t = 0; t < 8; t++) {
            int f = tid + t * 128;
            int r = f >> 3, c8 = (f & 7) * 8;
            int gr = i0 + r; if (gr > HW_ - 1) gr = HW_ - 1;
            int gc = j0 + c8; if (gc > KHW_ - 8) gc = KHW_ - 8;
            cp16(sb + 2 * KBUF + (uint32_t)((r * BST + c8) * 2),
                 bias_h + (size_t)gr * KHW_ + gc);
        }
    };

    load_tile(0, 0);
    cp_commit();

    float oacc[2][4][4];
    float c5[2][4];
    #pragma unroll
    for (int g = 0; g < 2; g++) {
        #pragma unroll
        for (int nf = 0; nf < 4; nf++)
            #pragma unroll
            for (int r = 0; r < 4; r++) oacc[g][nf][r] = 0.f;
        #pragma unroll
        for (int r = 0; r < 4; r++) c5[g][r] = 0.f;
    }
    const uint32_t bone = (lane < 4) ? 0x3C003C00u : 0u;
    uint32_t bones[2] = {bone, bone};

    const int rr = ((lane >> 3) & 1) * 8 + (lane & 7);
    const int ch = (lane >> 4) & 1;

    #pragma unroll 1
    for (int jt = 0; jt < 13; jt++) {
        cp_wait_all();
        __syncthreads();
        if (jt + 1 < 13) { load_tile((jt + 1) * 64, (jt + 1) & 1); cp_commit(); }

        const uint32_t sb = sbase + (jt & 1) * STAGEB;
        const uint32_t kbase = sb;
        const uint32_t vbase = sb + KBUF;
        const uint32_t bbase = sb + 2 * KBUF;

        #pragma unroll
        for (int g = 0; g < 2; g++) {
            // --- S = Q @ K^T (K frags reloaded per kk to cap reg peak) ---
            float s[8][4];
            #pragma unroll
            for (int nf = 0; nf < 8; nf++)
                #pragma unroll
                for (int r = 0; r < 4; r++) s[nf][r] = 0.f;

            #pragma unroll
            for (int kk = 0; kk < 2; kk++) {
                uint32_t kbf[8][2];
                int krow = (lane & 7) + ((lane >> 3) & 1) * 8;
                int ncol = ((lane >> 4) & 1) * 8;
                #pragma unroll
                for (int jg = 0; jg < 4; jg++) {
                    uint32_t r4[4];
                    ldm_x4_t(r4, kbase + (uint32_t)(((kk * 16 + krow) * KST + jg * 16 + ncol) * 2));
                    kbf[2 * jg][0] = r4[0]; kbf[2 * jg][1] = r4[1];
                    kbf[2 * jg + 1][0] = r4[2]; kbf[2 * jg + 1][1] = r4[3];
                }
                #pragma unroll
                for (int nf = 0; nf < 8; nf++)
                    mma_bf16(s[nf], qa[g][kk], kbf[nf]);
            }

            // --- softmax numerators via ldmatrix bias + f16x2 ex2 ---
            const int brow = w * 32 + g * 16 + rr;
            uint32_t pa[4][4];
            if (jt < 12) {
                #pragma unroll
                for (int cg = 0; cg < 4; cg++) {
                    uint32_t bb4[4];
                    ldm_x4(bb4, bbase + (uint32_t)((brow * BST + cg * 16 + ch * 8) * 2));
                    pa[cg][0] = bias_ex2(s[2 * cg][0],     s[2 * cg][1],     bb4[0]);
                    pa[cg][1] = bias_ex2(s[2 * cg][2],     s[2 * cg][3],     bb4[1]);
                    pa[cg][2] = bias_ex2(s[2 * cg + 1][0], s[2 * cg + 1][1], bb4[2]);
                    pa[cg][3] = bias_ex2(s[2 * cg + 1][2], s[2 * cg + 1][3], bb4[3]);
                }
            } else {
                // last tile: only cols 0..15 valid (784 = 12*64 + 16)
                uint32_t bb4[4];
                ldm_x4(bb4, bbase + (uint32_t)((brow * BST + ch * 8) * 2));
                pa[0][0] = bias_ex2(s[0][0], s[0][1], bb4[0]);
                pa[0][1] = bias_ex2(s[0][2], s[0][3], bb4[1]);
                pa[0][2] = bias_ex2(s[1][0], s[1][1], bb4[2]);
                pa[0][3] = bias_ex2(s[1][2], s[1][3], bb4[3]);
                #pragma unroll
                for (int cg = 1; cg < 4; cg++)
                    #pragma unroll
                    for (int r = 0; r < 4; r++) pa[cg][r] = 0u;
            }

            // --- O += P @ V, denom += P @ ones (JIT V fragments) ---
            #pragma unroll
            for (int kf = 0; kf < 4; kf++) {
                uint32_t vk[4][2];
                #pragma unroll
                for (int ng = 0; ng < 2; ng++) {
                    uint32_t r4[4];
                    ldm_x4(r4, vbase + (uint32_t)(((ng * 16 + rr) * KST + kf * 16 + ch * 8) * 2));
                    vk[2 * ng][0] = r4[0]; vk[2 * ng][1] = r4[2];
                    vk[2 * ng + 1][0] = r4[1]; vk[2 * ng + 1][1] = r4[3];
                }
                #pragma unroll
                for (int nf = 0; nf < 4; nf++)
                    mma_f16(oacc[g][nf], pa[kf], vk[nf]);
                mma_f16(c5[g], pa[kf], bones);
            }
        }
    }

    // --- epilogue: broadcast denominators, normalize, store (per group) ---
    int src = (lane >> 2) << 2;
    #pragma unroll
    for (int g = 0; g < 2; g++) {
        float l0 = __shfl_sync(0xffffffffu, c5[g][0], src);
        float l1 = __shfl_sync(0xffffffffu, c5[g][2], src);
        float inv0 = 1.f / l0, inv1 = 1.f / l1;
        int giA = i0 + w * 32 + g * 16 + (lane >> 2);
        int giB = giA + 8;
        #pragma unroll
        for (int nf = 0; nf < 4; nf++) {
            int col = h * 32 + nf * 8 + (lane & 3) * 2;
            if (giA < HW_)
                *(__nv_bfloat162*)(res + ((size_t)(b * HW_ + giA)) * 256 + col) =
                    __floats2bfloat162_rn(oacc[g][nf][0] * inv0, oacc[g][nf][1] * inv0);
            if (giB < HW_)
                *(__nv_bfloat162*)(res + ((size_t)(b * HW_ + giB)) * 256 + col) =
                    __floats2bfloat162_rn(oacc[g][nf][2] * inv1, oacc[g][nf][3] * inv1);
        }
    }
}

// ---------------------------------------------------------------------------
extern "C" void kernel_launch(void* const* d_in, const int* in_sizes, int n_in,
                              void* d_out, int out_size) {
    const float* x     = (const float*)d_in[0];
    const float* Wk_dw = (const float*)d_in[1];
    const float* bk_dw = (const float*)d_in[2];
    const float* Wv_dw = (const float*)d_in[3];
    const float* bv_dw = (const float*)d_in[4];
    const float* Wq    = (const float*)d_in[5];
    const float* bq    = (const float*)d_in[6];
    const float* Wk    = (const float*)d_in[7];
    const float* bk    = (const float*)d_in[8];
    const float* Wv    = (const float*)d_in[9];
    const float* bv    = (const float*)d_in[10];
    const float* Wo    = (const float*)d_in[11];
    const float* bo    = (const float*)d_in[12];
    const float* Bb    = (const float*)d_in[13];
    float* out = (float*)d_out;

    __nv_bfloat16 *qp, *kp, *resp, *xbfp;
    __half *vp, *bbfp;
    __nv_bfloat16 *wqp, *wop;
    float *cqp;
    cudaGetSymbolAddress((void**)&qp,   g_q);
    cudaGetSymbolAddress((void**)&kp,   g_k);
    cudaGetSymbolAddress((void**)&vp,   g_v);
    cudaGetSymbolAddress((void**)&resp, g_res);
    cudaGetSymbolAddress((void**)&xbfp, g_xbf);
    cudaGetSymbolAddress((void**)&bbfp, g_bbf);
    cudaGetSymbolAddress((void**)&wqp,  g_wq);
    cudaGetSymbolAddress((void**)&wop,  g_wo);
    cudaGetSymbolAddress((void**)&cqp,  g_cq);

    cudaFuncSetAttribute(attn_mma_kernel,
                         cudaFuncAttributeMaxDynamicSharedMemorySize, ATT_SMEM);

    cudaStream_t s1, s2;
    cudaStreamCreateWithFlags(&s1, cudaStreamNonBlocking);
    cudaStreamCreateWithFlags(&s2, cudaStreamNonBlocking);
    cudaEvent_t evRoot, evW, ev1, ev2;
    cudaEventCreateWithFlags(&evRoot, cudaEventDisableTiming);
    cudaEventCreateWithFlags(&evW,    cudaEventDisableTiming);
    cudaEventCreateWithFlags(&ev1,    cudaEventDisableTiming);
    cudaEventCreateWithFlags(&ev2,    cudaEventDisableTiming);

    cudaEventRecord(evRoot, 0);
    cudaStreamWaitEvent(s1, evRoot, 0);
    cudaStreamWaitEvent(s2, evRoot, 0);

    // s1: weight conversion first (unblocks everything), then bias conversion
    cvt_w_kernel<<<256, 256, 0, s1>>>(Wq, Wk, Wv, Wo);
    cudaEventRecord(evW, s1);
    cvt_bias<<<BIASN_ / 8 / 256, 256, 0, s1>>>(Bb);
    cudaEventRecord(ev1, s1);

    // s2: dwconv, then fused K+V projections
    dwconv_kernel<<<(B_ * C_ * KHW_ + 255) / 256, 256, 0, s2>>>(x, Wk_dw, bk_dw, Wv_dw, bv_dw);
    cudaStreamWaitEvent(s2, evW, 0);
    gemm_kv<<<dim3(7, 2, 16), 256, 0, s2>>>(bk, bv);
    cudaEventRecord(ev2, s2);

    // main: x conversion + stats, then Q projection
    cvt_x_stats<<<NPART_, 256>>>(x);
    cudaStreamWaitEvent(0, evW, 0);
    stats_final<<<1, 256>>>(bq);
    gemm_wx<<<dim3(25, 2, B_), 256>>>(wqp, xbfp, cqp, 1, HW_, qp);

    cudaStreamWaitEvent(0, ev1, 0);
    cudaStreamWaitEvent(0, ev2, 0);

    attn_mma_kernel<<<dim3(B_, HEADS_, 25), 128, ATT_SMEM>>>(qp, kp, vp, bbfp, resp);

    gemm_o<<<dim3(25, 2, B_), 256>>>(resp, wop, bo, x, out);

    cudaEventDestroy(evRoot);
    cudaEventDestroy(evW);
    cudaEventDestroy(ev1);
    cudaEventDestroy(ev2);
    cudaStreamDestroy(s1);
    cudaStreamDestroy(s2);
}

// round 16
// speedup vs baseline: 1.1475x; 1.0081x over previous
#include <cuda_runtime.h>
#include <cuda_bf16.h>
#include <cuda_fp16.h>
#include <math.h>
#include <stdint.h>

// Problem constants
#define B_   8
#define C_   256
#define H_   56
#define W_   56
#define HW_  3136        // 56*56
#define KHW_ 784         // 28*28
#define HEADS_ 8
#define NTOT_ 6422528    // B*C*HW
#define NPART_ 6272
#define BIASN_ 19668992  // HEADS*HW*KHW
#define EPS_ 1e-5
#define SCALE_ 0.17677669529663687f   // 1/sqrt(32)
#define LOG2E_ 1.4426950408889634f

// Scratch (static device arrays — allocation-free)
__device__ __nv_bfloat16 g_q[B_ * 256 * HW_];    // [b][hd][i]  (log2e-scaled)
__device__ __nv_bfloat16 g_k[B_ * 256 * KHW_];   // [b][hd][j]
__device__ __half        g_v[B_ * 256 * KHW_];   // [b][hd][j]  fp16
__device__ __nv_bfloat16 g_res[B_ * HW_ * 256];  // [b][i][hd]
__device__ __nv_bfloat16 g_ck[B_ * C_ * KHW_];
__device__ __nv_bfloat16 g_cv[B_ * C_ * KHW_];
__device__ __nv_bfloat16 g_xbf[NTOT_];
__device__ __half        g_bbf[BIASN_];          // bias*log2e in fp16
__device__ __nv_bfloat16 g_wq[65536], g_wk[65536], g_wv[65536], g_wo[65536];
__device__ float g_part[2 * NPART_];
__device__ float g_wqsum[256];
__device__ float g_stats[2];
__device__ float g_cq[256];

// ---------------------------------------------------------------------------
// asm helpers
// ---------------------------------------------------------------------------
__device__ __forceinline__ uint32_t smem_u32(const void* p) {
    return (uint32_t)__cvta_generic_to_shared(p);
}
__device__ __forceinline__ void ldm_x4(uint32_t* r, uint32_t addr) {
    asm volatile("ldmatrix.sync.aligned.m8n8.x4.shared.b16 {%0,%1,%2,%3}, [%4];"
        : "=r"(r[0]), "=r"(r[1]), "=r"(r[2]), "=r"(r[3]) : "r"(addr));
}
__device__ __forceinline__ void ldm_x4_t(uint32_t* r, uint32_t addr) {
    asm volatile("ldmatrix.sync.aligned.m8n8.x4.trans.shared.b16 {%0,%1,%2,%3}, [%4];"
        : "=r"(r[0]), "=r"(r[1]), "=r"(r[2]), "=r"(r[3]) : "r"(addr));
}
__device__ __forceinline__ void mma_bf16(float* d, const uint32_t* a, const uint32_t* b) {
    asm volatile(
        "mma.sync.aligned.m16n8k16.row.col.f32.bf16.bf16.f32 "
        "{%0,%1,%2,%3}, {%4,%5,%6,%7}, {%8,%9}, {%0,%1,%2,%3};"
        : "+f"(d[0]), "+f"(d[1]), "+f"(d[2]), "+f"(d[3])
        : "r"(a[0]), "r"(a[1]), "r"(a[2]), "r"(a[3]), "r"(b[0]), "r"(b[1]));
}
__device__ __forceinline__ void mma_f16(float* d, const uint32_t* a, const uint32_t* b) {
    asm volatile(
        "mma.sync.aligned.m16n8k16.row.col.f32.f16.f16.f32 "
        "{%0,%1,%2,%3}, {%4,%5,%6,%7}, {%8,%9}, {%0,%1,%2,%3};"
        : "+f"(d[0]), "+f"(d[1]), "+f"(d[2]), "+f"(d[3])
        : "r"(a[0]), "r"(a[1]), "r"(a[2]), "r"(a[3]), "r"(b[0]), "r"(b[1]));
}
__device__ __forceinline__ uint32_t bias_ex2(float lo, float hi, uint32_t bias2) {
    uint32_t t, u, r;
    asm("cvt.rn.f16x2.f32 %0, %1, %2;" : "=r"(t) : "f"(hi), "f"(lo));
    asm("add.f16x2 %0, %1, %2;" : "=r"(u) : "r"(t), "r"(bias2));
    asm("ex2.approx.f16x2 %0, %1;" : "=r"(r) : "r"(u));
    return r;
}
__device__ __forceinline__ void cp16(uint32_t dst, const void* src) {
    asm volatile("cp.async.cg.shared.global [%0], [%1], 16;" :: "r"(dst), "l"(src));
}
__device__ __forceinline__ void cp_commit() {
    asm volatile("cp.async.commit_group;" ::: "memory");
}
__device__ __forceinline__ void cp_wait_all() {
    asm volatile("cp.async.wait_group 0;" ::: "memory");
}

// ---------------------------------------------------------------------------
// Fused: x fp32 -> bf16 + LN partial sums
// ---------------------------------------------------------------------------
__global__ void cvt_x_stats(const float* __restrict__ x) {
    int tid = threadIdx.x;
    int i = blockIdx.x * 256 + tid;
    float4 v = ((const float4*)x)[i];
    __nv_bfloat162* o = (__nv_bfloat162*)(g_xbf + (size_t)i * 4);
    o[0] = __floats2bfloat162_rn(v.x, v.y);
    o[1] = __floats2bfloat162_rn(v.z, v.w);
    float s  = v.x + v.y + v.z + v.w;
    float ss = v.x * v.x + v.y * v.y + v.z * v.z + v.w * v.w;
    #pragma unroll
    for (int ofs = 16; ofs; ofs >>= 1) {
        s  += __shfl_xor_sync(0xffffffffu, s, ofs);
        ss += __shfl_xor_sync(0xffffffffu, ss, ofs);
    }
    __shared__ float sh[16];
    int w = tid >> 5, lane = tid & 31;
    if (lane == 0) { sh[w] = s; sh[8 + w] = ss; }
    __syncthreads();
    if (tid == 0) {
        float a = 0.f, b = 0.f;
        #pragma unroll
        for (int k = 0; k < 8; k++) { a += sh[k]; b += sh[8 + k]; }
        g_part[blockIdx.x] = a;
        g_part[NPART_ + blockIdx.x] = b;
    }
}

// ---------------------------------------------------------------------------
// Weight conversions (vectorized) + Wq rowsum
// ---------------------------------------------------------------------------
__global__ void cvt_w_kernel(const float* __restrict__ Wq, const float* __restrict__ Wk,
                             const float* __restrict__ Wv, const float* __restrict__ Wo) {
    int r = blockIdx.x, tid = threadIdx.x;
    int base = r * 256 + (tid & 63) * 4;
    int grp = tid >> 6;
    const float* src = (grp == 0) ? Wq : (grp == 1) ? Wk : (grp == 2) ? Wv : Wo;
    __nv_bfloat16* dst = (grp == 0) ? g_wq : (grp == 1) ? g_wk : (grp == 2) ? g_wv : g_wo;
    float4 v = *(const float4*)(src + base);
    *(__nv_bfloat162*)(dst + base)     = __floats2bfloat162_rn(v.x, v.y);
    *(__nv_bfloat162*)(dst + base + 2) = __floats2bfloat162_rn(v.z, v.w);
    float s = (grp == 0) ? (v.x + v.y) + (v.z + v.w) : 0.f;
    #pragma unroll
    for (int ofs = 16; ofs; ofs >>= 1) s += __shfl_xor_sync(0xffffffffu, s, ofs);
    __shared__ float sh[8];
    if ((tid & 31) == 0) sh[tid >> 5] = s;
    __syncthreads();
    if (tid == 0) g_wqsum[r] = sh[0] + sh[1];
}

// ---------------------------------------------------------------------------
// Bias fp32 -> fp16 * log2e
// ---------------------------------------------------------------------------
__global__ void cvt_bias(const float* __restrict__ Bb) {
    size_t i = (size_t)blockIdx.x * 256 + threadIdx.x;
    float4 a = ((const float4*)Bb)[2 * i];
    float4 b = ((const float4*)Bb)[2 * i + 1];
    __half2* o = (__half2*)(g_bbf + i * 8);
    o[0] = __floats2half2_rn(a.x * LOG2E_, a.y * LOG2E_);
    o[1] = __floats2half2_rn(a.z * LOG2E_, a.w * LOG2E_);
    o[2] = __floats2half2_rn(b.x * LOG2E_, b.y * LOG2E_);
    o[3] = __floats2half2_rn(b.z * LOG2E_, b.w * LOG2E_);
}

// ---------------------------------------------------------------------------
// Finalize mu/rstd + folded Q bias
// ---------------------------------------------------------------------------
__global__ void stats_final(const float* __restrict__ bq) {
    int tid = threadIdx.x;
    const float4* p4  = (const float4*)g_part;
    const float4* ps4 = (const float4*)(g_part + NPART_);
    double s = 0.0, ss = 0.0;
    for (int i = tid; i < NPART_ / 4; i += 256) {
        float4 a = p4[i];
        float4 b = ps4[i];
        s  += (double)((a.x + a.y) + (a.z + a.w));
        ss += (double)((b.x + b.y) + (b.z + b.w));
    }
    __shared__ double shs[256], shss[256];
    shs[tid] = s; shss[tid] = ss;
    __syncthreads();
    for (int o = 128; o; o >>= 1) {
        if (tid < o) { shs[tid] += shs[tid + o]; shss[tid] += shss[tid + o]; }
        __syncthreads();
    }
    __shared__ float mu_s, rstd_s;
    if (tid == 0) {
        double N = (double)NTOT_;
        double mu = shs[0] / N;
        double var = shss[0] / N - mu * mu;
        float rstd = (float)(1.0 / sqrt(var + EPS_));
        g_stats[0] = (float)mu;
        g_stats[1] = rstd;
        mu_s = (float)mu; rstd_s = rstd;
    }
    __syncthreads();
    g_cq[tid] = bq[tid] - rstd_s * mu_s * g_wqsum[tid];
}

// ---------------------------------------------------------------------------
// Depthwise 3x3 stride-2 conv (K and V paths fused), bf16 output
// ---------------------------------------------------------------------------
__global__ void dwconv_kernel(const float* __restrict__ x,
                              const float* __restrict__ wk, const float* __restrict__ bkd,
                              const float* __restrict__ wv, const float* __restrict__ bvd) {
    int idx = blockIdx.x * blockDim.x + threadIdx.x;
    if (idx >= B_ * C_ * KHW_) return;
    int ox = idx % 28;
    int oy = (idx / 28) % 28;
    int c  = (idx / KHW_) % C_;
    int b  = idx / (KHW_ * C_);
    const float* xp = x + ((size_t)(b * C_ + c)) * HW_;
    float ak = 0.f, av = 0.f;
    #pragma unroll
    for (int ky = 0; ky < 3; ky++) {
        int iy = oy * 2 + ky - 1;
        if (iy < 0 || iy >= H_) continue;
        #pragma unroll
        for (int kx = 0; kx < 3; kx++) {
            int ix = ox * 2 + kx - 1;
            if (ix < 0 || ix >= W_) continue;
            float xv = xp[iy * W_ + ix];
            ak += xv * wk[c * 9 + ky * 3 + kx];
            av += xv * wv[c * 9 + ky * 3 + kx];
        }
    }
    g_ck[idx] = __float2bfloat16(ak + bkd[c]);
    g_cv[idx] = __float2bfloat16(av + bvd[c]);
}

// ---------------------------------------------------------------------------
// bf16 mma GEMM (2-stage cp.async): Q projection (mode 1)
// ---------------------------------------------------------------------------
#define WST 40
#define XST 136
__global__ void __launch_bounds__(256, 2) gemm_wx(
    const __nv_bfloat16* __restrict__ W, const __nv_bfloat16* __restrict__ X,
    const float* __restrict__ cvec, int mode, int Mt,
    void* __restrict__ outp)
{
    __shared__ __align__(16) __nv_bfloat16 Ws[2][128 * WST];
    __shared__ __align__(16) __nv_bfloat16 Xs[2][32 * XST];
    const int P0 = blockIdx.x * 128;
    const int R0 = blockIdx.y * 128;
    const int b  = blockIdx.z;
    const __nv_bfloat16* Xb = X + (size_t)b * 256 * Mt;
    const int tid = threadIdx.x, lane = tid & 31, w = tid >> 5;
    const int wR = (w >> 2) * 64, wP = (w & 3) * 32;

    float c[4][4][4];
    #pragma unroll
    for (int i = 0; i < 4; i++)
        #pragma unroll
        for (int j = 0; j < 4; j++)
            #pragma unroll
            for (int r = 0; r < 4; r++) c[i][j][r] = 0.f;

    const uint32_t wsb = smem_u32(Ws), xsb = smem_u32(Xs);

    auto load_stage = [&](int k0, int buf) {
        uint32_t wd = wsb + buf * (128 * WST * 2);
        uint32_t xd = xsb + buf * (32 * XST * 2);
        #pragma unroll
        for (int t = 0; t < 2; t++) {
            int f = tid + t * 256;
            int r = f >> 2, cc = (f & 3) * 8;
            cp16(wd + (uint32_t)((r * WST + cc) * 2),
                 W + (size_t)(R0 + r) * 256 + k0 + cc);
        }
        #pragma unroll
        for (int t = 0; t < 2; t++) {
            int f = tid + t * 256;
            int kk = f >> 4, p = (f & 15) * 8;
            int gp = P0 + p; if (gp > Mt - 8) gp = Mt - 8;
            cp16(xd + (uint32_t)((kk * XST + p) * 2),
                 Xb + (size_t)(k0 + kk) * Mt + gp);
        }
    };

    load_stage(0, 0);
    cp_commit();

    for (int s = 0; s < 8; s++) {
        cp_wait_all();
        __syncthreads();
        if (s + 1 < 8) { load_stage((s + 1) * 32, (s + 1) & 1); cp_commit(); }
        const int buf = s & 1;
        const uint32_t wb = wsb + buf * (128 * WST * 2);
        const uint32_t xb = xsb + buf * (32 * XST * 2);

        #pragma unroll
        for (int kk = 0; kk < 2; kk++) {
            uint32_t af[4][4], bf[4][2];
            {
                int rr = ((lane >> 3) & 1) * 8 + (lane & 7);
                int ch = (lane >> 4) & 1;
                #pragma unroll
                for (int rf = 0; rf < 4; rf++)
                    ldm_x4(af[rf], wb + (uint32_t)(((wR + rf * 16 + rr) * WST + kk * 16 + ch * 8) * 2));
            }
            {
                int krow = (lane & 7) + ((lane >> 3) & 1) * 8;
                int pc = ((lane >> 4) & 1) * 8;
                #pragma unroll
                for (int pf = 0; pf < 2; pf++) {
                    uint32_t r4[4];
                    ldm_x4_t(r4, xb + (uint32_t)(((kk * 16 + krow) * XST + wP + pf * 16 + pc) * 2));
                    bf[2 * pf][0] = r4[0]; bf[2 * pf][1] = r4[1];
                    bf[2 * pf + 1][0] = r4[2]; bf[2 * pf + 1][1] = r4[3];
                }
            }
            #pragma unroll
            for (int rf = 0; rf < 4; rf++)
                #pragma unroll
                for (int pg = 0; pg < 4; pg++)
                    mma_bf16(c[rf][pg], af[rf], bf[pg]);
        }
        __syncthreads();
    }

    float a1 = 1.f, a2 = 1.f;
    if (mode == 1) { a1 = g_stats[1] * SCALE_ * LOG2E_; a2 = SCALE_ * LOG2E_; }
    #pragma unroll
    for (int rf = 0; rf < 4; rf++) {
        int R = R0 + wR + rf * 16 + (lane >> 2);
        float cv1 = a2 * cvec[R], cv2 = a2 * cvec[R + 8];
        #pragma unroll
        for (int pg = 0; pg < 4; pg++) {
            int P = P0 + wP + pg * 8 + (lane & 3) * 2;
            if (P < Mt) {
                __nv_bfloat16* ob = (__nv_bfloat16*)outp + (size_t)b * 256 * Mt;
                *(__nv_bfloat162*)(ob + (size_t)R * Mt + P) =
                    __floats2bfloat162_rn(a1 * c[rf][pg][0] + cv1, a1 * c[rf][pg][1] + cv1);
                *(__nv_bfloat162*)(ob + (size_t)(R + 8) * Mt + P) =
                    __floats2bfloat162_rn(a1 * c[rf][pg][2] + cv2, a1 * c[rf][pg][3] + cv2);
            }
        }
    }
}

// Fused K+V projection: blockIdx.z = b*2 + isV.
__global__ void __launch_bounds__(256, 2) gemm_kv(
    const float* __restrict__ bk, const float* __restrict__ bv)
{
    const int z = blockIdx.z;
    const int b = z >> 1, isV = z & 1;
    const __nv_bfloat16* W = isV ? g_wv : g_wk;
    const __nv_bfloat16* X = (isV ? g_cv : g_ck) + (size_t)b * 256 * KHW_;
    const float* cvec = isV ? bv : bk;

    __shared__ __align__(16) __nv_bfloat16 Ws[2][128 * WST];
    __shared__ __align__(16) __nv_bfloat16 Xs[2][32 * XST];
    const int P0 = blockIdx.x * 128;
    const int R0 = blockIdx.y * 128;
    const int tid = threadIdx.x, lane = tid & 31, w = tid >> 5;
    const int wR = (w >> 2) * 64, wP = (w & 3) * 32;

    float c[4][4][4];
    #pragma unroll
    for (int i = 0; i < 4; i++)
        #pragma unroll
        for (int j = 0; j < 4; j++)
            #pragma unroll
            for (int r = 0; r < 4; r++) c[i][j][r] = 0.f;

    const uint32_t wsb = smem_u32(Ws), xsb = smem_u32(Xs);

    auto load_stage = [&](int k0, int buf) {
        uint32_t wd = wsb + buf * (128 * WST * 2);
        uint32_t xd = xsb + buf * (32 * XST * 2);
        #pragma unroll
        for (int t = 0; t < 2; t++) {
            int f = tid + t * 256;
            int r = f >> 2, cc = (f & 3) * 8;
            cp16(wd + (uint32_t)((r * WST + cc) * 2),
                 W + (size_t)(R0 + r) * 256 + k0 + cc);
        }
        #pragma unroll
        for (int t = 0; t < 2; t++) {
            int f = tid + t * 256;
            int kk = f >> 4, p = (f & 15) * 8;
            int gp = P0 + p; if (gp > KHW_ - 8) gp = KHW_ - 8;
            cp16(xd + (uint32_t)((kk * XST + p) * 2),
                 X + (size_t)(k0 + kk) * KHW_ + gp);
        }
    };

    load_stage(0, 0);
    cp_commit();

    for (int s = 0; s < 8; s++) {
        cp_wait_all();
        __syncthreads();
        if (s + 1 < 8) { load_stage((s + 1) * 32, (s + 1) & 1); cp_commit(); }
        const int buf = s & 1;
        const uint32_t wb = wsb + buf * (128 * WST * 2);
        const uint32_t xb = xsb + buf * (32 * XST * 2);

        #pragma unroll
        for (int kk = 0; kk < 2; kk++) {
            uint32_t af[4][4], bf[4][2];
            {
                int rr = ((lane >> 3) & 1) * 8 + (lane & 7);
                int ch = (lane >> 4) & 1;
                #pragma unroll
                for (int rf = 0; rf < 4; rf++)
                    ldm_x4(af[rf], wb + (uint32_t)(((wR + rf * 16 + rr) * WST + kk * 16 + ch * 8) * 2));
            }
            {
                int krow = (lane & 7) + ((lane >> 3) & 1) * 8;
                int pc = ((lane >> 4) & 1) * 8;
                #pragma unroll
                for (int pf = 0; pf < 2; pf++) {
                    uint32_t r4[4];
                    ldm_x4_t(r4, xb + (uint32_t)(((kk * 16 + krow) * XST + wP + pf * 16 + pc) * 2));
                    bf[2 * pf][0] = r4[0]; bf[2 * pf][1] = r4[1];
                    bf[2 * pf + 1][0] = r4[2]; bf[2 * pf + 1][1] = r4[3];
                }
            }
            #pragma unroll
            for (int rf = 0; rf < 4; rf++)
                #pragma unroll
                for (int pg = 0; pg < 4; pg++)
                    mma_bf16(c[rf][pg], af[rf], bf[pg]);
        }
        __syncthreads();
    }

    #pragma unroll
    for (int rf = 0; rf < 4; rf++) {
        int R = R0 + wR + rf * 16 + (lane >> 2);
        float cv1 = cvec[R], cv2 = cvec[R + 8];
        #pragma unroll
        for (int pg = 0; pg < 4; pg++) {
            int P = P0 + wP + pg * 8 + (lane & 3) * 2;
            if (P < KHW_) {
                if (isV) {
                    __half* ob = g_v + (size_t)b * 256 * KHW_;
                    *(__half2*)(ob + (size_t)R * KHW_ + P) =
                        __floats2half2_rn(c[rf][pg][0] + cv1, c[rf][pg][1] + cv1);
                    *(__half2*)(ob + (size_t)(R + 8) * KHW_ + P) =
                        __floats2half2_rn(c[rf][pg][2] + cv2, c[rf][pg][3] + cv2);
                } else {
                    __nv_bfloat16* ob = g_k + (size_t)b * 256 * KHW_;
                    *(__nv_bfloat162*)(ob + (size_t)R * KHW_ + P) =
                        __floats2bfloat162_rn(c[rf][pg][0] + cv1, c[rf][pg][1] + cv1);
                    *(__nv_bfloat162*)(ob + (size_t)(R + 8) * KHW_ + P) =
                        __floats2bfloat162_rn(c[rf][pg][2] + cv2, c[rf][pg][3] + cv2);
                }
            }
        }
    }
}

// ---------------------------------------------------------------------------
// O projection mma GEMM (2-stage cp.async) + fused bias + flat residual add
// ---------------------------------------------------------------------------
__global__ void __launch_bounds__(256, 2) gemm_o(
    const __nv_bfloat16* __restrict__ A, const __nv_bfloat16* __restrict__ Wo,
    const float* __restrict__ bo, const float* __restrict__ x,
    float* __restrict__ out)
{
    __shared__ __align__(16) __nv_bfloat16 As[2][128 * WST];
    __shared__ __align__(16) __nv_bfloat16 Bs[2][128 * WST];
    const int I0 = blockIdx.x * 128;
    const int N0 = blockIdx.y * 128;
    const int b  = blockIdx.z;
    const int tid = threadIdx.x, lane = tid & 31, w = tid >> 5;
    const int wI = (w >> 2) * 64, wN = (w & 3) * 32;

    float c[4][4][4];
    #pragma unroll
    for (int i = 0; i < 4; i++)
        #pragma unroll
        for (int j = 0; j < 4; j++)
            #pragma unroll
            for (int r = 0; r < 4; r++) c[i][j][r] = 0.f;

    const uint32_t asb = smem_u32(As), bsb = smem_u32(Bs);

    auto load_stage = [&](int k0, int buf) {
        uint32_t ad = asb + buf * (128 * WST * 2);
        uint32_t bd = bsb + buf * (128 * WST * 2);
        #pragma unroll
        for (int t = 0; t < 2; t++) {
            int f = tid + t * 256;
            int i = f >> 2, cc = (f & 3) * 8;
            int gi = I0 + i; if (gi > HW_ - 1) gi = HW_ - 1;
            cp16(ad + (uint32_t)((i * WST + cc) * 2),
                 A + ((size_t)(b * HW_) + gi) * 256 + k0 + cc);
        }
        #pragma unroll
        for (int t = 0; t < 2; t++) {
            int f = tid + t * 256;
            int n = f >> 2, cc = (f & 3) * 8;
            cp16(bd + (uint32_t)((n * WST + cc) * 2),
                 Wo + (size_t)(N0 + n) * 256 + k0 + cc);
        }
    };

    load_stage(0, 0);
    cp_commit();

    for (int s = 0; s < 8; s++) {
        cp_wait_all();
        __syncthreads();
        if (s + 1 < 8) { load_stage((s + 1) * 32, (s + 1) & 1); cp_commit(); }
        const int buf = s & 1;
        const uint32_t ab = asb + buf * (128 * WST * 2);
        const uint32_t bb = bsb + buf * (128 * WST * 2);

        #pragma unroll
        for (int kk = 0; kk < 2; kk++) {
            int rr = ((lane >> 3) & 1) * 8 + (lane & 7);
            int ch = (lane >> 4) & 1;
            uint32_t af[4][4], bf[4][2];
            #pragma unroll
            for (int mf = 0; mf < 4; mf++)
                ldm_x4(af[mf], ab + (uint32_t)(((wI + mf * 16 + rr) * WST + kk * 16 + ch * 8) * 2));
            #pragma unroll
            for (int ng = 0; ng < 2; ng++) {
                uint32_t r4[4];
                ldm_x4(r4, bb + (uint32_t)(((wN + ng * 16 + rr) * WST + kk * 16 + ch * 8) * 2));
                bf[2 * ng][0] = r4[0]; bf[2 * ng][1] = r4[2];
                bf[2 * ng + 1][0] = r4[1]; bf[2 * ng + 1][1] = r4[3];
            }
            #pragma unroll
            for (int mf = 0; mf < 4; mf++)
                #pragma unroll
                for (int nf = 0; nf < 4; nf++)
                    mma_bf16(c[mf][nf], af[mf], bf[nf]);
        }
        __syncthreads();
    }

    #pragma unroll
    for (int mf = 0; mf < 4; mf++) {
        int i1 = I0 + wI + mf * 16 + (lane >> 2);
        int i2 = i1 + 8;
        #pragma unroll
        for (int nf = 0; nf < 4; nf++) {
            int n = N0 + wN + nf * 8 + (lane & 3) * 2;
            float b0v = bo[n], b1v = bo[n + 1];
            if (i1 < HW_) {
                size_t flat = (size_t)b * (256 * HW_) + (size_t)i1 * 256 + n;
                float2 xv = *(const float2*)(x + flat);
                *(float2*)(out + flat) =
                    make_float2(c[mf][nf][0] + b0v + xv.x, c[mf][nf][1] + b1v + xv.y);
            }
            if (i2 < HW_) {
                size_t flat = (size_t)b * (256 * HW_) + (size_t)i2 * 256 + n;
                float2 xv = *(const float2*)(x + flat);
                *(float2*)(out + flat) =
                    make_float2(c[mf][nf][2] + b0v + xv.x, c[mf][nf][3] + b1v + xv.y);
            }
        }
    }
}

// ---------------------------------------------------------------------------
// Flash attention, 4 blocks/SM, SPILL-FREE: S/softmax processed in two
// 32-column j-halves so peak register liveness fits 128 without spilling.
// Q staged in stage-0 buffer then recycled. 4 warps x 32 q-rows.
// ---------------------------------------------------------------------------
#define QST 136
#define KST 72
#define BST 72
#define KBUF (32 * KST * 2)          // 4608
#define BBUF (128 * BST * 2)         // 18432
#define STAGEB (2 * KBUF + BBUF)     // 27648
#define ATT_SMEM (2 * STAGEB)        // 55296

__global__ void __launch_bounds__(128, 4) attn_mma_kernel(
    const __nv_bfloat16* __restrict__ qb, const __nv_bfloat16* __restrict__ kb,
    const __half* __restrict__ vb, const __half* __restrict__ bias,
    __nv_bfloat16* __restrict__ res)
{
    extern __shared__ __align__(16) char smraw[];
    __nv_bfloat16* Qs = (__nv_bfloat16*)smraw;    // temporary, recycled

    const int b = blockIdx.x, h = blockIdx.y;
    const int i0 = blockIdx.z * 128;
    const int tid = threadIdx.x, lane = tid & 31, w = tid >> 5;

    const __nv_bfloat16* qsrc = qb + ((size_t)b * 256 + h * 32) * HW_;
    const __nv_bfloat16* ksrc = kb + ((size_t)b * 256 + h * 32) * KHW_;
    const __half*        vsrc = vb + ((size_t)b * 256 + h * 32) * KHW_;
    const __half*        bias_h = bias + (size_t)h * HW_ * KHW_;

    const uint32_t sbase = smem_u32(smraw);

    // --- Stage Q temporarily at smem offset 0, extract fragments, recycle ---
    #pragma unroll
    for (int f = tid; f < 512; f += 128) {
        int d = f >> 4, ii = (f & 15) * 8;
        int gi = i0 + ii; if (gi > HW_ - 8) gi = HW_ - 8;
        *(uint4*)&Qs[d * QST + ii] = *(const uint4*)(qsrc + (size_t)d * HW_ + gi);
    }
    __syncthreads();

    uint32_t qa[2][2][4];
    {
        int krow = (lane & 7) + ((lane >> 4) & 1) * 8;
        #pragma unroll
        for (int g = 0; g < 2; g++) {
            int mcol = w * 32 + g * 16 + ((lane >> 3) & 1) * 8;
            #pragma unroll
            for (int kk = 0; kk < 2; kk++)
                ldm_x4_t(qa[g][kk], sbase + (uint32_t)(((kk * 16 + krow) * QST + mcol) * 2));
        }
    }
    __syncthreads();   // all warps done reading Q; region now reusable

    auto load_tile = [&](int j0, int buf) {
        uint32_t sb = sbase + buf * STAGEB;
        #pragma unroll
        for (int t = 0; t < 2; t++) {
            int f = tid + t * 128;
            int d = f >> 3, jj = (f & 7) * 8;
            int gj = j0 + jj; if (gj > KHW_ - 8) gj = KHW_ - 8;
            cp16(sb + (uint32_t)((d * KST + jj) * 2), ksrc + (size_t)d * KHW_ + gj);
            cp16(sb + KBUF + (uint32_t)((d * KST + jj) * 2), vsrc + (size_t)d * KHW_ + gj);
        }
        #pragma unroll
        for (int t = 0; t < 8; t++) {
            int f = tid + t * 128;
            int r = f >> 3, c8 = (f & 7) * 8;
            int gr = i0 + r; if (gr > HW_ - 1) gr = HW_ - 1;
            int gc = j0 + c8; if (gc > KHW_ - 8) gc = KHW_ - 8;
            cp16(sb + 2 * KBUF + (uint32_t)((r * BST + c8) * 2),
                 bias_h + (size_t)gr * KHW_ + gc);
        }
    };

    load_tile(0, 0);
    cp_commit();

    float oacc[2][4][4];
    float c5[2][4];
    #pragma unroll
    for (int g = 0; g < 2; g++) {
        #pragma unroll
        for (int nf = 0; nf < 4; nf++)
            #pragma unroll
            for (int r = 0; r < 4; r++) oacc[g][nf][r] = 0.f;
        #pragma unroll
        for (int r = 0; r < 4; r++) c5[g][r] = 0.f;
    }
    const uint32_t bone = (lane < 4) ? 0x3C003C00u : 0u;
    uint32_t bones[2] = {bone, bone};

    const int rr = ((lane >> 3) & 1) * 8 + (lane & 7);
    const int ch = (lane >> 4) & 1;

    #pragma unroll 1
    for (int jt = 0; jt < 13; jt++) {
        cp_wait_all();
        __syncthreads();
        if (jt + 1 < 13) { load_tile((jt + 1) * 64, (jt + 1) & 1); cp_commit(); }

        const uint32_t sb = sbase + (jt & 1) * STAGEB;
        const uint32_t kbase = sb;
        const uint32_t vbase = sb + KBUF;
        const uint32_t bbase = sb + 2 * KBUF;

        #pragma unroll
        for (int g = 0; g < 2; g++) {
            const int brow = w * 32 + g * 16 + rr;
            uint32_t pa[4][4];

            if (jt < 12) {
                // --- two 32-column halves: S-mma + softmax per half.
                //     Peak transient = s[4][4] + kbf[4][2] + bb4 (~28 regs). ---
                #pragma unroll
                for (int half = 0; half < 2; half++) {
                    float s[4][4];
                    #pragma unroll
                    for (int nf = 0; nf < 4; nf++)
                        #pragma unroll
                        for (int r = 0; r < 4; r++) s[nf][r] = 0.f;

                    #pragma unroll
                    for (int kk = 0; kk < 2; kk++) {
                        uint32_t kbf[4][2];
                        int krow = (lane & 7) + ((lane >> 3) & 1) * 8;
                        int ncol = ((lane >> 4) & 1) * 8;
                        #pragma unroll
                        for (int jg2 = 0; jg2 < 2; jg2++) {
                            uint32_t r4[4];
                            ldm_x4_t(r4, kbase + (uint32_t)(((kk * 16 + krow) * KST
                                        + (half * 2 + jg2) * 16 + ncol) * 2));
                            kbf[2 * jg2][0] = r4[0]; kbf[2 * jg2][1] = r4[1];
                            kbf[2 * jg2 + 1][0] = r4[2]; kbf[2 * jg2 + 1][1] = r4[3];
                        }
                        #pragma unroll
                        for (int nf = 0; nf < 4; nf++)
                            mma_bf16(s[nf], qa[g][kk], kbf[nf]);
                    }

                    #pragma unroll
                    for (int cg2 = 0; cg2 < 2; cg2++) {
                        int cg = half * 2 + cg2;
                        uint32_t bb4[4];
                        ldm_x4(bb4, bbase + (uint32_t)((brow * BST + cg * 16 + ch * 8) * 2));
                        pa[cg][0] = bias_ex2(s[2 * cg2][0],     s[2 * cg2][1],     bb4[0]);
                        pa[cg][1] = bias_ex2(s[2 * cg2][2],     s[2 * cg2][3],     bb4[1]);
                        pa[cg][2] = bias_ex2(s[2 * cg2 + 1][0], s[2 * cg2 + 1][1], bb4[2]);
                        pa[cg][3] = bias_ex2(s[2 * cg2 + 1][2], s[2 * cg2 + 1][3], bb4[3]);
                    }
                }
            } else {
                // last tile: only cols 0..15 valid (784 = 12*64 + 16)
                float s[2][4];
                #pragma unroll
                for (int nf = 0; nf < 2; nf++)
                    #pragma unroll
                    for (int r = 0; r < 4; r++) s[nf][r] = 0.f;
                #pragma unroll
                for (int kk = 0; kk < 2; kk++) {
                    uint32_t kbf[2][2];
                    int krow = (lane & 7) + ((lane >> 3) & 1) * 8;
                    int ncol = ((lane >> 4) & 1) * 8;
                    uint32_t r4[4];
                    ldm_x4_t(r4, kbase + (uint32_t)(((kk * 16 + krow) * KST + ncol) * 2));
                    kbf[0][0] = r4[0]; kbf[0][1] = r4[1];
                    kbf[1][0] = r4[2]; kbf[1][1] = r4[3];
                    #pragma unroll
                    for (int nf = 0; nf < 2; nf++)
                        mma_bf16(s[nf], qa[g][kk], kbf[nf]);
                }
                uint32_t bb4[4];
                ldm_x4(bb4, bbase + (uint32_t)((brow * BST + ch * 8) * 2));
                pa[0][0] = bias_ex2(s[0][0], s[0][1], bb4[0]);
                pa[0][1] = bias_ex2(s[0][2], s[0][3], bb4[1]);
                pa[0][2] = bias_ex2(s[1][0], s[1][1], bb4[2]);
                pa[0][3] = bias_ex2(s[1][2], s[1][3], bb4[3]);
                #pragma unroll
                for (int cg = 1; cg < 4; cg++)
                    #pragma unroll
                    for (int r = 0; r < 4; r++) pa[cg][r] = 0u;
            }

            // --- O += P @ V, denom += P @ ones (JIT V fragments) ---
            #pragma unroll
            for (int kf = 0; kf < 4; kf++) {
                uint32_t vk[4][2];
                #pragma unroll
                for (int ng = 0; ng < 2; ng++) {
                    uint32_t r4[4];
                    ldm_x4(r4, vbase + (uint32_t)(((ng * 16 + rr) * KST + kf * 16 + ch * 8) * 2));
                    vk[2 * ng][0] = r4[0]; vk[2 * ng][1] = r4[2];
                    vk[2 * ng + 1][0] = r4[1]; vk[2 * ng + 1][1] = r4[3];
                }
                #pragma unroll
                for (int nf = 0; nf < 4; nf++)
                    mma_f16(oacc[g][nf], pa[kf], vk[nf]);
                mma_f16(c5[g], pa[kf], bones);
            }
        }
    }

    // --- epilogue: broadcast denominators, normalize, store (per group) ---
    int src = (lane >> 2) << 2;
    #pragma unroll
    for (int g = 0; g < 2; g++) {
        float l0 = __shfl_sync(0xffffffffu, c5[g][0], src);
        float l1 = __shfl_sync(0xffffffffu, c5[g][2], src);
        float inv0 = 1.f / l0, inv1 = 1.f / l1;
        int giA = i0 + w * 32 + g * 16 + (lane >> 2);
        int giB = giA + 8;
        #pragma unroll
        for (int nf = 0; nf < 4; nf++) {
            int col = h * 32 + nf * 8 + (lane & 3) * 2;
            if (giA < HW_)
                *(__nv_bfloat162*)(res + ((size_t)(b * HW_ + giA)) * 256 + col) =
                    __floats2bfloat162_rn(oacc[g][nf][0] * inv0, oacc[g][nf][1] * inv0);
            if (giB < HW_)
                *(__nv_bfloat162*)(res + ((size_t)(b * HW_ + giB)) * 256 + col) =
                    __floats2bfloat162_rn(oacc[g][nf][2] * inv1, oacc[g][nf][3] * inv1);
        }
    }
}

// ---------------------------------------------------------------------------
extern "C" void kernel_launch(void* const* d_in, const int* in_sizes, int n_in,
                              void* d_out, int out_size) {
    const float* x     = (const float*)d_in[0];
    const float* Wk_dw = (const float*)d_in[1];
    const float* bk_dw = (const float*)d_in[2];
    const float* Wv_dw = (const float*)d_in[3];
    const float* bv_dw = (const float*)d_in[4];
    const float* Wq    = (const float*)d_in[5];
    const float* bq    = (const float*)d_in[6];
    const float* Wk    = (const float*)d_in[7];
    const float* bk    = (const float*)d_in[8];
    const float* Wv    = (const float*)d_in[9];
    const float* bv    = (const float*)d_in[10];
    const float* Wo    = (const float*)d_in[11];
    const float* bo    = (const float*)d_in[12];
    const float* Bb    = (const float*)d_in[13];
    float* out = (float*)d_out;

    __nv_bfloat16 *qp, *kp, *resp, *xbfp;
    __half *vp, *bbfp;
    __nv_bfloat16 *wqp, *wop;
    float *cqp;
    cudaGetSymbolAddress((void**)&qp,   g_q);
    cudaGetSymbolAddress((void**)&kp,   g_k);
    cudaGetSymbolAddress((void**)&vp,   g_v);
    cudaGetSymbolAddress((void**)&resp, g_res);
    cudaGetSymbolAddress((void**)&xbfp, g_xbf);
    cudaGetSymbolAddress((void**)&bbfp, g_bbf);
    cudaGetSymbolAddress((void**)&wqp,  g_wq);
    cudaGetSymbolAddress((void**)&wop,  g_wo);
    cudaGetSymbolAddress((void**)&cqp,  g_cq);

    cudaFuncSetAttribute(attn_mma_kernel,
                         cudaFuncAttributeMaxDynamicSharedMemorySize, ATT_SMEM);

    cudaStream_t s1, s2;
    cudaStreamCreateWithFlags(&s1, cudaStreamNonBlocking);
    cudaStreamCreateWithFlags(&s2, cudaStreamNonBlocking);
    cudaEvent_t evRoot, evW, ev1, ev2;
    cudaEventCreateWithFlags(&evRoot, cudaEventDisableTiming);
    cudaEventCreateWithFlags(&evW,    cudaEventDisableTiming);
    cudaEventCreateWithFlags(&ev1,    cudaEventDisableTiming);
    cudaEventCreateWithFlags(&ev2,    cudaEventDisableTiming);

    cudaEventRecord(evRoot, 0);
    cudaStreamWaitEvent(s1, evRoot, 0);
    cudaStreamWaitEvent(s2, evRoot, 0);

    // s1: weight conversion first (unblocks everything), then bias conversion
    cvt_w_kernel<<<256, 256, 0, s1>>>(Wq, Wk, Wv, Wo);
    cudaEventRecord(evW, s1);
    cvt_bias<<<BIASN_ / 8 / 256, 256, 0, s1>>>(Bb);
    cudaEventRecord(ev1, s1);

    // s2: dwconv, then fused K+V projections
    dwconv_kernel<<<(B_ * C_ * KHW_ + 255) / 256, 256, 0, s2>>>(x, Wk_dw, bk_dw, Wv_dw, bv_dw);
    cudaStreamWaitEvent(s2, evW, 0);
    gemm_kv<<<dim3(7, 2, 16), 256, 0, s2>>>(bk, bv);
    cudaEventRecord(ev2, s2);

    // main: x conversion + stats, then Q projection
    cvt_x_stats<<<NPART_, 256>>>(x);
    cudaStreamWaitEvent(0, evW, 0);
    stats_final<<<1, 256>>>(bq);
    gemm_wx<<<dim3(25, 2, B_), 256>>>(wqp, xbfp, cqp, 1, HW_, qp);

    cudaStreamWaitEvent(0, ev1, 0);
    cudaStreamWaitEvent(0, ev2, 0);

    attn_mma_kernel<<<dim3(B_, HEADS_, 25), 128, ATT_SMEM>>>(qp, kp, vp, bbfp, resp);

    gemm_o<<<dim3(25, 2, B_), 256>>>(resp, wop, bo, x, out);

    cudaEventDestroy(evRoot);
    cudaEventDestroy(evW);
    cudaEventDestroy(ev1);
    cudaEventDestroy(ev2);
    cudaStreamDestroy(s1);
    cudaStreamDestroy(s2);
}

// round 17
// speedup vs baseline: 1.1479x; 1.0003x over previous
#include <cuda_runtime.h>
#include <cuda_bf16.h>
#include <cuda_fp16.h>
#include <math.h>
#include <stdint.h>

// Problem constants
#define B_   8
#define C_   256
#define H_   56
#define W_   56
#define HW_  3136        // 56*56
#define KHW_ 784         // 28*28
#define HEADS_ 8
#define NTOT_ 6422528    // B*C*HW
#define NPART_ 6272
#define BIASN_ 19668992  // HEADS*HW*KHW
#define EPS_ 1e-5
#define SCALE_ 0.17677669529663687f   // 1/sqrt(32)
#define LOG2E_ 1.4426950408889634f

// Scratch (static device arrays — allocation-free)
__device__ __nv_bfloat16 g_q[B_ * 256 * HW_];    // [b][hd][i]  (log2e-scaled)
__device__ __nv_bfloat16 g_k[B_ * 256 * KHW_];   // [b][hd][j]
__device__ __half        g_v[B_ * 256 * KHW_];   // [b][hd][j]  fp16
__device__ __nv_bfloat16 g_res[B_ * HW_ * 256];  // [b][i][hd]
__device__ __nv_bfloat16 g_ck[B_ * C_ * KHW_];
__device__ __nv_bfloat16 g_cv[B_ * C_ * KHW_];
__device__ __nv_bfloat16 g_xbf[NTOT_];
__device__ __half        g_bbf[BIASN_];          // bias*log2e in fp16
__device__ __nv_bfloat16 g_wq[65536], g_wk[65536], g_wv[65536], g_wo[65536];
__device__ float g_part[2 * NPART_];
__device__ float g_wqsum[256];
__device__ float g_stats[2];
__device__ float g_cq[256];

// ---------------------------------------------------------------------------
// asm helpers
// ---------------------------------------------------------------------------
__device__ __forceinline__ uint32_t smem_u32(const void* p) {
    return (uint32_t)__cvta_generic_to_shared(p);
}
__device__ __forceinline__ void ldm_x4(uint32_t* r, uint32_t addr) {
    asm volatile("ldmatrix.sync.aligned.m8n8.x4.shared.b16 {%0,%1,%2,%3}, [%4];"
        : "=r"(r[0]), "=r"(r[1]), "=r"(r[2]), "=r"(r[3]) : "r"(addr));
}
__device__ __forceinline__ void ldm_x4_t(uint32_t* r, uint32_t addr) {
    asm volatile("ldmatrix.sync.aligned.m8n8.x4.trans.shared.b16 {%0,%1,%2,%3}, [%4];"
        : "=r"(r[0]), "=r"(r[1]), "=r"(r[2]), "=r"(r[3]) : "r"(addr));
}
__device__ __forceinline__ void mma_bf16(float* d, const uint32_t* a, const uint32_t* b) {
    asm volatile(
        "mma.sync.aligned.m16n8k16.row.col.f32.bf16.bf16.f32 "
        "{%0,%1,%2,%3}, {%4,%5,%6,%7}, {%8,%9}, {%0,%1,%2,%3};"
        : "+f"(d[0]), "+f"(d[1]), "+f"(d[2]), "+f"(d[3])
        : "r"(a[0]), "r"(a[1]), "r"(a[2]), "r"(a[3]), "r"(b[0]), "r"(b[1]));
}
__device__ __forceinline__ void mma_f16(float* d, const uint32_t* a, const uint32_t* b) {
    asm volatile(
        "mma.sync.aligned.m16n8k16.row.col.f32.f16.f16.f32 "
        "{%0,%1,%2,%3}, {%4,%5,%6,%7}, {%8,%9}, {%0,%1,%2,%3};"
        : "+f"(d[0]), "+f"(d[1]), "+f"(d[2]), "+f"(d[3])
        : "r"(a[0]), "r"(a[1]), "r"(a[2]), "r"(a[3]), "r"(b[0]), "r"(b[1]));
}
__device__ __forceinline__ uint32_t bias_ex2(float lo, float hi, uint32_t bias2) {
    uint32_t t, u, r;
    asm("cvt.rn.f16x2.f32 %0, %1, %2;" : "=r"(t) : "f"(hi), "f"(lo));
    asm("add.f16x2 %0, %1, %2;" : "=r"(u) : "r"(t), "r"(bias2));
    asm("ex2.approx.f16x2 %0, %1;" : "=r"(r) : "r"(u));
    return r;
}
__device__ __forceinline__ void cp16(uint32_t dst, const void* src) {
    asm volatile("cp.async.cg.shared.global [%0], [%1], 16;" :: "r"(dst), "l"(src));
}
__device__ __forceinline__ void cp_commit() {
    asm volatile("cp.async.commit_group;" ::: "memory");
}
__device__ __forceinline__ void cp_wait_all() {
    asm volatile("cp.async.wait_group 0;" ::: "memory");
}

// ---------------------------------------------------------------------------
// Fused: x fp32 -> bf16 + LN partial sums
// ---------------------------------------------------------------------------
__global__ void cvt_x_stats(const float* __restrict__ x) {
    int tid = threadIdx.x;
    int i = blockIdx.x * 256 + tid;
    float4 v = ((const float4*)x)[i];
    __nv_bfloat162* o = (__nv_bfloat162*)(g_xbf + (size_t)i * 4);
    o[0] = __floats2bfloat162_rn(v.x, v.y);
    o[1] = __floats2bfloat162_rn(v.z, v.w);
    float s  = v.x + v.y + v.z + v.w;
    float ss = v.x * v.x + v.y * v.y + v.z * v.z + v.w * v.w;
    #pragma unroll
    for (int ofs = 16; ofs; ofs >>= 1) {
        s  += __shfl_xor_sync(0xffffffffu, s, ofs);
        ss += __shfl_xor_sync(0xffffffffu, ss, ofs);
    }
    __shared__ float sh[16];
    int w = tid >> 5, lane = tid & 31;
    if (lane == 0) { sh[w] = s; sh[8 + w] = ss; }
    __syncthreads();
    if (tid == 0) {
        float a = 0.f, b = 0.f;
        #pragma unroll
        for (int k = 0; k < 8; k++) { a += sh[k]; b += sh[8 + k]; }
        g_part[blockIdx.x] = a;
        g_part[NPART_ + blockIdx.x] = b;
    }
}

// ---------------------------------------------------------------------------
// Weight conversions (vectorized) + Wq rowsum
// ---------------------------------------------------------------------------
__global__ void cvt_w_kernel(const float* __restrict__ Wq, const float* __restrict__ Wk,
                             const float* __restrict__ Wv, const float* __restrict__ Wo) {
    int r = blockIdx.x, tid = threadIdx.x;
    int base = r * 256 + (tid & 63) * 4;
    int grp = tid >> 6;
    const float* src = (grp == 0) ? Wq : (grp == 1) ? Wk : (grp == 2) ? Wv : Wo;
    __nv_bfloat16* dst = (grp == 0) ? g_wq : (grp == 1) ? g_wk : (grp == 2) ? g_wv : g_wo;
    float4 v = *(const float4*)(src + base);
    *(__nv_bfloat162*)(dst + base)     = __floats2bfloat162_rn(v.x, v.y);
    *(__nv_bfloat162*)(dst + base + 2) = __floats2bfloat162_rn(v.z, v.w);
    float s = (grp == 0) ? (v.x + v.y) + (v.z + v.w) : 0.f;
    #pragma unroll
    for (int ofs = 16; ofs; ofs >>= 1) s += __shfl_xor_sync(0xffffffffu, s, ofs);
    __shared__ float sh[8];
    if ((tid & 31) == 0) sh[tid >> 5] = s;
    __syncthreads();
    if (tid == 0) g_wqsum[r] = sh[0] + sh[1];
}

// ---------------------------------------------------------------------------
// Bias fp32 -> fp16 * log2e
// ---------------------------------------------------------------------------
__global__ void cvt_bias(const float* __restrict__ Bb) {
    size_t i = (size_t)blockIdx.x * 256 + threadIdx.x;
    float4 a = ((const float4*)Bb)[2 * i];
    float4 b = ((const float4*)Bb)[2 * i + 1];
    __half2* o = (__half2*)(g_bbf + i * 8);
    o[0] = __floats2half2_rn(a.x * LOG2E_, a.y * LOG2E_);
    o[1] = __floats2half2_rn(a.z * LOG2E_, a.w * LOG2E_);
    o[2] = __floats2half2_rn(b.x * LOG2E_, b.y * LOG2E_);
    o[3] = __floats2half2_rn(b.z * LOG2E_, b.w * LOG2E_);
}

// ---------------------------------------------------------------------------
// Finalize mu/rstd + folded Q bias
// ---------------------------------------------------------------------------
__global__ void stats_final(const float* __restrict__ bq) {
    int tid = threadIdx.x;
    const float4* p4  = (const float4*)g_part;
    const float4* ps4 = (const float4*)(g_part + NPART_);
    double s = 0.0, ss = 0.0;
    for (int i = tid; i < NPART_ / 4; i += 256) {
        float4 a = p4[i];
        float4 b = ps4[i];
        s  += (double)((a.x + a.y) + (a.z + a.w));
        ss += (double)((b.x + b.y) + (b.z + b.w));
    }
    __shared__ double shs[256], shss[256];
    shs[tid] = s; shss[tid] = ss;
    __syncthreads();
    for (int o = 128; o; o >>= 1) {
        if (tid < o) { shs[tid] += shs[tid + o]; shss[tid] += shss[tid + o]; }
        __syncthreads();
    }
    __shared__ float mu_s, rstd_s;
    if (tid == 0) {
        double N = (double)NTOT_;
        double mu = shs[0] / N;
        double var = shss[0] / N - mu * mu;
        float rstd = (float)(1.0 / sqrt(var + EPS_));
        g_stats[0] = (float)mu;
        g_stats[1] = rstd;
        mu_s = (float)mu; rstd_s = rstd;
    }
    __syncthreads();
    g_cq[tid] = bq[tid] - rstd_s * mu_s * g_wqsum[tid];
}

// ---------------------------------------------------------------------------
// Depthwise 3x3 stride-2 conv (K and V paths fused), bf16 output
// ---------------------------------------------------------------------------
__global__ void dwconv_kernel(const float* __restrict__ x,
                              const float* __restrict__ wk, const float* __restrict__ bkd,
                              const float* __restrict__ wv, const float* __restrict__ bvd) {
    int idx = blockIdx.x * blockDim.x + threadIdx.x;
    if (idx >= B_ * C_ * KHW_) return;
    int ox = idx % 28;
    int oy = (idx / 28) % 28;
    int c  = (idx / KHW_) % C_;
    int b  = idx / (KHW_ * C_);
    const float* xp = x + ((size_t)(b * C_ + c)) * HW_;
    float ak = 0.f, av = 0.f;
    #pragma unroll
    for (int ky = 0; ky < 3; ky++) {
        int iy = oy * 2 + ky - 1;
        if (iy < 0 || iy >= H_) continue;
        #pragma unroll
        for (int kx = 0; kx < 3; kx++) {
            int ix = ox * 2 + kx - 1;
            if (ix < 0 || ix >= W_) continue;
            float xv = xp[iy * W_ + ix];
            ak += xv * wk[c * 9 + ky * 3 + kx];
            av += xv * wv[c * 9 + ky * 3 + kx];
        }
    }
    g_ck[idx] = __float2bfloat16(ak + bkd[c]);
    g_cv[idx] = __float2bfloat16(av + bvd[c]);
}

// ---------------------------------------------------------------------------
// bf16 mma GEMM (2-stage cp.async): Q projection (mode 1)
// ---------------------------------------------------------------------------
#define WST 40
#define XST 136
__global__ void __launch_bounds__(256, 2) gemm_wx(
    const __nv_bfloat16* __restrict__ W, const __nv_bfloat16* __restrict__ X,
    const float* __restrict__ cvec, int mode, int Mt,
    void* __restrict__ outp)
{
    __shared__ __align__(16) __nv_bfloat16 Ws[2][128 * WST];
    __shared__ __align__(16) __nv_bfloat16 Xs[2][32 * XST];
    const int P0 = blockIdx.x * 128;
    const int R0 = blockIdx.y * 128;
    const int b  = blockIdx.z;
    const __nv_bfloat16* Xb = X + (size_t)b * 256 * Mt;
    const int tid = threadIdx.x, lane = tid & 31, w = tid >> 5;
    const int wR = (w >> 2) * 64, wP = (w & 3) * 32;

    float c[4][4][4];
    #pragma unroll
    for (int i = 0; i < 4; i++)
        #pragma unroll
        for (int j = 0; j < 4; j++)
            #pragma unroll
            for (int r = 0; r < 4; r++) c[i][j][r] = 0.f;

    const uint32_t wsb = smem_u32(Ws), xsb = smem_u32(Xs);

    auto load_stage = [&](int k0, int buf) {
        uint32_t wd = wsb + buf * (128 * WST * 2);
        uint32_t xd = xsb + buf * (32 * XST * 2);
        #pragma unroll
        for (int t = 0; t < 2; t++) {
            int f = tid + t * 256;
            int r = f >> 2, cc = (f & 3) * 8;
            cp16(wd + (uint32_t)((r * WST + cc) * 2),
                 W + (size_t)(R0 + r) * 256 + k0 + cc);
        }
        #pragma unroll
        for (int t = 0; t < 2; t++) {
            int f = tid + t * 256;
            int kk = f >> 4, p = (f & 15) * 8;
            int gp = P0 + p; if (gp > Mt - 8) gp = Mt - 8;
            cp16(xd + (uint32_t)((kk * XST + p) * 2),
                 Xb + (size_t)(k0 + kk) * Mt + gp);
        }
    };

    load_stage(0, 0);
    cp_commit();

    for (int s = 0; s < 8; s++) {
        cp_wait_all();
        __syncthreads();
        if (s + 1 < 8) { load_stage((s + 1) * 32, (s + 1) & 1); cp_commit(); }
        const int buf = s & 1;
        const uint32_t wb = wsb + buf * (128 * WST * 2);
        const uint32_t xb = xsb + buf * (32 * XST * 2);

        #pragma unroll
        for (int kk = 0; kk < 2; kk++) {
            uint32_t af[4][4], bf[4][2];
            {
                int rr = ((lane >> 3) & 1) * 8 + (lane & 7);
                int ch = (lane >> 4) & 1;
                #pragma unroll
                for (int rf = 0; rf < 4; rf++)
                    ldm_x4(af[rf], wb + (uint32_t)(((wR + rf * 16 + rr) * WST + kk * 16 + ch * 8) * 2));
            }
            {
                int krow = (lane & 7) + ((lane >> 3) & 1) * 8;
                int pc = ((lane >> 4) & 1) * 8;
                #pragma unroll
                for (int pf = 0; pf < 2; pf++) {
                    uint32_t r4[4];
                    ldm_x4_t(r4, xb + (uint32_t)(((kk * 16 + krow) * XST + wP + pf * 16 + pc) * 2));
                    bf[2 * pf][0] = r4[0]; bf[2 * pf][1] = r4[1];
                    bf[2 * pf + 1][0] = r4[2]; bf[2 * pf + 1][1] = r4[3];
                }
            }
            #pragma unroll
            for (int rf = 0; rf < 4; rf++)
                #pragma unroll
                for (int pg = 0; pg < 4; pg++)
                    mma_bf16(c[rf][pg], af[rf], bf[pg]);
        }
        __syncthreads();
    }

    float a1 = 1.f, a2 = 1.f;
    if (mode == 1) { a1 = g_stats[1] * SCALE_ * LOG2E_; a2 = SCALE_ * LOG2E_; }
    #pragma unroll
    for (int rf = 0; rf < 4; rf++) {
        int R = R0 + wR + rf * 16 + (lane >> 2);
        float cv1 = a2 * cvec[R], cv2 = a2 * cvec[R + 8];
        #pragma unroll
        for (int pg = 0; pg < 4; pg++) {
            int P = P0 + wP + pg * 8 + (lane & 3) * 2;
            if (P < Mt) {
                __nv_bfloat16* ob = (__nv_bfloat16*)outp + (size_t)b * 256 * Mt;
                *(__nv_bfloat162*)(ob + (size_t)R * Mt + P) =
                    __floats2bfloat162_rn(a1 * c[rf][pg][0] + cv1, a1 * c[rf][pg][1] + cv1);
                *(__nv_bfloat162*)(ob + (size_t)(R + 8) * Mt + P) =
                    __floats2bfloat162_rn(a1 * c[rf][pg][2] + cv2, a1 * c[rf][pg][3] + cv2);
            }
        }
    }
}

// Fused K+V projection: blockIdx.z = b*2 + isV.
__global__ void __launch_bounds__(256, 2) gemm_kv(
    const float* __restrict__ bk, const float* __restrict__ bv)
{
    const int z = blockIdx.z;
    const int b = z >> 1, isV = z & 1;
    const __nv_bfloat16* W = isV ? g_wv : g_wk;
    const __nv_bfloat16* X = (isV ? g_cv : g_ck) + (size_t)b * 256 * KHW_;
    const float* cvec = isV ? bv : bk;

    __shared__ __align__(16) __nv_bfloat16 Ws[2][128 * WST];
    __shared__ __align__(16) __nv_bfloat16 Xs[2][32 * XST];
    const int P0 = blockIdx.x * 128;
    const int R0 = blockIdx.y * 128;
    const int tid = threadIdx.x, lane = tid & 31, w = tid >> 5;
    const int wR = (w >> 2) * 64, wP = (w & 3) * 32;

    float c[4][4][4];
    #pragma unroll
    for (int i = 0; i < 4; i++)
        #pragma unroll
        for (int j = 0; j < 4; j++)
            #pragma unroll
            for (int r = 0; r < 4; r++) c[i][j][r] = 0.f;

    const uint32_t wsb = smem_u32(Ws), xsb = smem_u32(Xs);

    auto load_stage = [&](int k0, int buf) {
        uint32_t wd = wsb + buf * (128 * WST * 2);
        uint32_t xd = xsb + buf * (32 * XST * 2);
        #pragma unroll
        for (int t = 0; t < 2; t++) {
            int f = tid + t * 256;
            int r = f >> 2, cc = (f & 3) * 8;
            cp16(wd + (uint32_t)((r * WST + cc) * 2),
                 W + (size_t)(R0 + r) * 256 + k0 + cc);
        }
        #pragma unroll
        for (int t = 0; t < 2; t++) {
            int f = tid + t * 256;
            int kk = f >> 4, p = (f & 15) * 8;
            int gp = P0 + p; if (gp > KHW_ - 8) gp = KHW_ - 8;
            cp16(xd + (uint32_t)((kk * XST + p) * 2),
                 X + (size_t)(k0 + kk) * KHW_ + gp);
        }
    };

    load_stage(0, 0);
    cp_commit();

    for (int s = 0; s < 8; s++) {
        cp_wait_all();
        __syncthreads();
        if (s + 1 < 8) { load_stage((s + 1) * 32, (s + 1) & 1); cp_commit(); }
        const int buf = s & 1;
        const uint32_t wb = wsb + buf * (128 * WST * 2);
        const uint32_t xb = xsb + buf * (32 * XST * 2);

        #pragma unroll
        for (int kk = 0; kk < 2; kk++) {
            uint32_t af[4][4], bf[4][2];
            {
                int rr = ((lane >> 3) & 1) * 8 + (lane & 7);
                int ch = (lane >> 4) & 1;
                #pragma unroll
                for (int rf = 0; rf < 4; rf++)
                    ldm_x4(af[rf], wb + (uint32_t)(((wR + rf * 16 + rr) * WST + kk * 16 + ch * 8) * 2));
            }
            {
                int krow = (lane & 7) + ((lane >> 3) & 1) * 8;
                int pc = ((lane >> 4) & 1) * 8;
                #pragma unroll
                for (int pf = 0; pf < 2; pf++) {
                    uint32_t r4[4];
                    ldm_x4_t(r4, xb + (uint32_t)(((kk * 16 + krow) * XST + wP + pf * 16 + pc) * 2));
                    bf[2 * pf][0] = r4[0]; bf[2 * pf][1] = r4[1];
                    bf[2 * pf + 1][0] = r4[2]; bf[2 * pf + 1][1] = r4[3];
                }
            }
            #pragma unroll
            for (int rf = 0; rf < 4; rf++)
                #pragma unroll
                for (int pg = 0; pg < 4; pg++)
                    mma_bf16(c[rf][pg], af[rf], bf[pg]);
        }
        __syncthreads();
    }

    #pragma unroll
    for (int rf = 0; rf < 4; rf++) {
        int R = R0 + wR + rf * 16 + (lane >> 2);
        float cv1 = cvec[R], cv2 = cvec[R + 8];
        #pragma unroll
        for (int pg = 0; pg < 4; pg++) {
            int P = P0 + wP + pg * 8 + (lane & 3) * 2;
            if (P < KHW_) {
                if (isV) {
                    __half* ob = g_v + (size_t)b * 256 * KHW_;
                    *(__half2*)(ob + (size_t)R * KHW_ + P) =
                        __floats2half2_rn(c[rf][pg][0] + cv1, c[rf][pg][1] + cv1);
                    *(__half2*)(ob + (size_t)(R + 8) * KHW_ + P) =
                        __floats2half2_rn(c[rf][pg][2] + cv2, c[rf][pg][3] + cv2);
                } else {
                    __nv_bfloat16* ob = g_k + (size_t)b * 256 * KHW_;
                    *(__nv_bfloat162*)(ob + (size_t)R * KHW_ + P) =
                        __floats2bfloat162_rn(c[rf][pg][0] + cv1, c[rf][pg][1] + cv1);
                    *(__nv_bfloat162*)(ob + (size_t)(R + 8) * KHW_ + P) =
                        __floats2bfloat162_rn(c[rf][pg][2] + cv2, c[rf][pg][3] + cv2);
                }
            }
        }
    }
}

// ---------------------------------------------------------------------------
// O projection mma GEMM (2-stage cp.async) + fused bias + flat residual add
// ---------------------------------------------------------------------------
__global__ void __launch_bounds__(256, 2) gemm_o(
    const __nv_bfloat16* __restrict__ A, const __nv_bfloat16* __restrict__ Wo,
    const float* __restrict__ bo, const float* __restrict__ x,
    float* __restrict__ out)
{
    __shared__ __align__(16) __nv_bfloat16 As[2][128 * WST];
    __shared__ __align__(16) __nv_bfloat16 Bs[2][128 * WST];
    const int I0 = blockIdx.x * 128;
    const int N0 = blockIdx.y * 128;
    const int b  = blockIdx.z;
    const int tid = threadIdx.x, lane = tid & 31, w = tid >> 5;
    const int wI = (w >> 2) * 64, wN = (w & 3) * 32;

    float c[4][4][4];
    #pragma unroll
    for (int i = 0; i < 4; i++)
        #pragma unroll
        for (int j = 0; j < 4; j++)
            #pragma unroll
            for (int r = 0; r < 4; r++) c[i][j][r] = 0.f;

    const uint32_t asb = smem_u32(As), bsb = smem_u32(Bs);

    auto load_stage = [&](int k0, int buf) {
        uint32_t ad = asb + buf * (128 * WST * 2);
        uint32_t bd = bsb + buf * (128 * WST * 2);
        #pragma unroll
        for (int t = 0; t < 2; t++) {
            int f = tid + t * 256;
            int i = f >> 2, cc = (f & 3) * 8;
            int gi = I0 + i; if (gi > HW_ - 1) gi = HW_ - 1;
            cp16(ad + (uint32_t)((i * WST + cc) * 2),
                 A + ((size_t)(b * HW_) + gi) * 256 + k0 + cc);
        }
        #pragma unroll
        for (int t = 0; t < 2; t++) {
            int f = tid + t * 256;
            int n = f >> 2, cc = (f & 3) * 8;
            cp16(bd + (uint32_t)((n * WST + cc) * 2),
                 Wo + (size_t)(N0 + n) * 256 + k0 + cc);
        }
    };

    load_stage(0, 0);
    cp_commit();

    for (int s = 0; s < 8; s++) {
        cp_wait_all();
        __syncthreads();
        if (s + 1 < 8) { load_stage((s + 1) * 32, (s + 1) & 1); cp_commit(); }
        const int buf = s & 1;
        const uint32_t ab = asb + buf * (128 * WST * 2);
        const uint32_t bb = bsb + buf * (128 * WST * 2);

        #pragma unroll
        for (int kk = 0; kk < 2; kk++) {
            int rr = ((lane >> 3) & 1) * 8 + (lane & 7);
            int ch = (lane >> 4) & 1;
            uint32_t af[4][4], bf[4][2];
            #pragma unroll
            for (int mf = 0; mf < 4; mf++)
                ldm_x4(af[mf], ab + (uint32_t)(((wI + mf * 16 + rr) * WST + kk * 16 + ch * 8) * 2));
            #pragma unroll
            for (int ng = 0; ng < 2; ng++) {
                uint32_t r4[4];
                ldm_x4(r4, bb + (uint32_t)(((wN + ng * 16 + rr) * WST + kk * 16 + ch * 8) * 2));
                bf[2 * ng][0] = r4[0]; bf[2 * ng][1] = r4[2];
                bf[2 * ng + 1][0] = r4[1]; bf[2 * ng + 1][1] = r4[3];
            }
            #pragma unroll
            for (int mf = 0; mf < 4; mf++)
                #pragma unroll
                for (int nf = 0; nf < 4; nf++)
                    mma_bf16(c[mf][nf], af[mf], bf[nf]);
        }
        __syncthreads();
    }

    #pragma unroll
    for (int mf = 0; mf < 4; mf++) {
        int i1 = I0 + wI + mf * 16 + (lane >> 2);
        int i2 = i1 + 8;
        #pragma unroll
        for (int nf = 0; nf < 4; nf++) {
            int n = N0 + wN + nf * 8 + (lane & 3) * 2;
            float b0v = bo[n], b1v = bo[n + 1];
            if (i1 < HW_) {
                size_t flat = (size_t)b * (256 * HW_) + (size_t)i1 * 256 + n;
                float2 xv = *(const float2*)(x + flat);
                *(float2*)(out + flat) =
                    make_float2(c[mf][nf][0] + b0v + xv.x, c[mf][nf][1] + b1v + xv.y);
            }
            if (i2 < HW_) {
                size_t flat = (size_t)b * (256 * HW_) + (size_t)i2 * 256 + n;
                float2 xv = *(const float2*)(x + flat);
                *(float2*)(out + flat) =
                    make_float2(c[mf][nf][2] + b0v + xv.x, c[mf][nf][3] + b1v + xv.y);
            }
        }
    }
}

// ---------------------------------------------------------------------------
// Flash attention, TWO BATCHES PER BLOCK sharing the bias tile, with the
// spill-free half-split softmax. 8 warps x 16 rows x 2 batches.
// smem/stage: K0,K1,V0,V1 (4x4608) + shared bias 128x72 fp16 (18432) = 36864;
// 2 stages = 73728 B -> 2 blocks/SM (16 warps). Bias L2 traffic HALVED.
// Persistent regs: oacc 32 + c5 8 + qa 16 = 56; transient ~45 -> no spills.
// ---------------------------------------------------------------------------
#define QST 136
#define KST 72
#define BST 72
#define KBUF (32 * KST * 2)          // 4608
#define BBUF (128 * BST * 2)         // 18432
#define STAGEB (4 * KBUF + BBUF)     // 36864
#define ATT_SMEM (2 * STAGEB)        // 73728

__global__ void __launch_bounds__(256, 2) attn_mma_kernel(
    const __nv_bfloat16* __restrict__ qb, const __nv_bfloat16* __restrict__ kb,
    const __half* __restrict__ vb, const __half* __restrict__ bias,
    __nv_bfloat16* __restrict__ res)
{
    extern __shared__ __align__(16) char smraw[];
    __nv_bfloat16* Qs = (__nv_bfloat16*)smraw;    // temporary, recycled

    const int b0 = blockIdx.x * 2, h = blockIdx.y;
    const int i0 = blockIdx.z * 128;
    const int tid = threadIdx.x, lane = tid & 31, w = tid >> 5;

    const __half* bias_h = bias + (size_t)h * HW_ * KHW_;
    const uint32_t sbase = smem_u32(smraw);

    // --- Stage both batches' Q temporarily (17408 B fits in stage 0),
    //     extract fragments, recycle region ---
    #pragma unroll
    for (int bat = 0; bat < 2; bat++) {
        const __nv_bfloat16* qsrc = qb + ((size_t)(b0 + bat) * 256 + h * 32) * HW_;
        #pragma unroll
        for (int f = tid; f < 512; f += 256) {
            int d = f >> 4, ii = (f & 15) * 8;
            int gi = i0 + ii; if (gi > HW_ - 8) gi = HW_ - 8;
            *(uint4*)&Qs[bat * (32 * QST) + d * QST + ii] =
                *(const uint4*)(qsrc + (size_t)d * HW_ + gi);
        }
    }
    __syncthreads();

    uint32_t qa[2][2][4];   // [bat][kk]
    {
        int krow = (lane & 7) + ((lane >> 4) & 1) * 8;
        int mcol = w * 16 + ((lane >> 3) & 1) * 8;
        #pragma unroll
        for (int bat = 0; bat < 2; bat++)
            #pragma unroll
            for (int kk = 0; kk < 2; kk++)
                ldm_x4_t(qa[bat][kk], sbase +
                    (uint32_t)((bat * 32 * QST + (kk * 16 + krow) * QST + mcol) * 2));
    }
    __syncthreads();   // region reusable

    auto load_tile = [&](int j0, int buf) {
        uint32_t sb = sbase + buf * STAGEB;
        {
            int d = tid >> 3, jj = (tid & 7) * 8;
            int gj = j0 + jj; if (gj > KHW_ - 8) gj = KHW_ - 8;
            #pragma unroll
            for (int bat = 0; bat < 2; bat++) {
                const __nv_bfloat16* ksrc = kb + ((size_t)(b0 + bat) * 256 + h * 32) * KHW_;
                const __half*        vsrc = vb + ((size_t)(b0 + bat) * 256 + h * 32) * KHW_;
                cp16(sb + bat * KBUF + (uint32_t)((d * KST + jj) * 2),
                     ksrc + (size_t)d * KHW_ + gj);
                cp16(sb + (2 + bat) * KBUF + (uint32_t)((d * KST + jj) * 2),
                     vsrc + (size_t)d * KHW_ + gj);
            }
        }
        #pragma unroll
        for (int t = 0; t < 4; t++) {          // shared bias [128 r][64 j]
            int f = tid + t * 256;
            int r = f >> 3, c8 = (f & 7) * 8;
            int gr = i0 + r; if (gr > HW_ - 1) gr = HW_ - 1;
            int gc = j0 + c8; if (gc > KHW_ - 8) gc = KHW_ - 8;
            cp16(sb + 4 * KBUF + (uint32_t)((r * BST + c8) * 2),
                 bias_h + (size_t)gr * KHW_ + gc);
        }
    };

    load_tile(0, 0);
    cp_commit();

    float oacc[2][4][4];
    float c5[2][4];
    #pragma unroll
    for (int bat = 0; bat < 2; bat++) {
        #pragma unroll
        for (int nf = 0; nf < 4; nf++)
            #pragma unroll
            for (int r = 0; r < 4; r++) oacc[bat][nf][r] = 0.f;
        #pragma unroll
        for (int r = 0; r < 4; r++) c5[bat][r] = 0.f;
    }
    const uint32_t bone = (lane < 4) ? 0x3C003C00u : 0u;
    uint32_t bones[2] = {bone, bone};

    const int rr = ((lane >> 3) & 1) * 8 + (lane & 7);
    const int ch = (lane >> 4) & 1;
    const int brow = w * 16 + rr;

    #pragma unroll 1
    for (int jt = 0; jt < 13; jt++) {
        cp_wait_all();
        __syncthreads();
        if (jt + 1 < 13) { load_tile((jt + 1) * 64, (jt + 1) & 1); cp_commit(); }

        const uint32_t sb = sbase + (jt & 1) * STAGEB;
        const uint32_t bbase = sb + 4 * KBUF;

        #pragma unroll
        for (int bat = 0; bat < 2; bat++) {
            const uint32_t kbase = sb + bat * KBUF;
            const uint32_t vbase = sb + (2 + bat) * KBUF;
            uint32_t pa[4][4];

            if (jt < 12) {
                // --- two 32-column halves: S-mma + softmax per half ---
                #pragma unroll
                for (int half = 0; half < 2; half++) {
                    float s[4][4];
                    #pragma unroll
                    for (int nf = 0; nf < 4; nf++)
                        #pragma unroll
                        for (int r = 0; r < 4; r++) s[nf][r] = 0.f;

                    #pragma unroll
                    for (int kk = 0; kk < 2; kk++) {
                        uint32_t kbf[4][2];
                        int krow = (lane & 7) + ((lane >> 3) & 1) * 8;
                        int ncol = ((lane >> 4) & 1) * 8;
                        #pragma unroll
                        for (int jg2 = 0; jg2 < 2; jg2++) {
                            uint32_t r4[4];
                            ldm_x4_t(r4, kbase + (uint32_t)(((kk * 16 + krow) * KST
                                        + (half * 2 + jg2) * 16 + ncol) * 2));
                            kbf[2 * jg2][0] = r4[0]; kbf[2 * jg2][1] = r4[1];
                            kbf[2 * jg2 + 1][0] = r4[2]; kbf[2 * jg2 + 1][1] = r4[3];
                        }
                        #pragma unroll
                        for (int nf = 0; nf < 4; nf++)
                            mma_bf16(s[nf], qa[bat][kk], kbf[nf]);
                    }

                    #pragma unroll
                    for (int cg2 = 0; cg2 < 2; cg2++) {
                        int cg = half * 2 + cg2;
                        uint32_t bb4[4];
                        ldm_x4(bb4, bbase + (uint32_t)((brow * BST + cg * 16 + ch * 8) * 2));
                        pa[cg][0] = bias_ex2(s[2 * cg2][0],     s[2 * cg2][1],     bb4[0]);
                        pa[cg][1] = bias_ex2(s[2 * cg2][2],     s[2 * cg2][3],     bb4[1]);
                        pa[cg][2] = bias_ex2(s[2 * cg2 + 1][0], s[2 * cg2 + 1][1], bb4[2]);
                        pa[cg][3] = bias_ex2(s[2 * cg2 + 1][2], s[2 * cg2 + 1][3], bb4[3]);
                    }
                }
            } else {
                // last tile: only cols 0..15 valid (784 = 12*64 + 16)
                float s[2][4];
                #pragma unroll
                for (int nf = 0; nf < 2; nf++)
                    #pragma unroll
                    for (int r = 0; r < 4; r++) s[nf][r] = 0.f;
                #pragma unroll
                for (int kk = 0; kk < 2; kk++) {
                    uint32_t kbf[2][2];
                    int krow = (lane & 7) + ((lane >> 3) & 1) * 8;
                    int ncol = ((lane >> 4) & 1) * 8;
                    uint32_t r4[4];
                    ldm_x4_t(r4, kbase + (uint32_t)(((kk * 16 + krow) * KST + ncol) * 2));
                    kbf[0][0] = r4[0]; kbf[0][1] = r4[1];
                    kbf[1][0] = r4[2]; kbf[1][1] = r4[3];
                    #pragma unroll
                    for (int nf = 0; nf < 2; nf++)
                        mma_bf16(s[nf], qa[bat][kk], kbf[nf]);
                }
                uint32_t bb4[4];
                ldm_x4(bb4, bbase + (uint32_t)((brow * BST + ch * 8) * 2));
                pa[0][0] = bias_ex2(s[0][0], s[0][1], bb4[0]);
                pa[0][1] = bias_ex2(s[0][2], s[0][3], bb4[1]);
                pa[0][2] = bias_ex2(s[1][0], s[1][1], bb4[2]);
                pa[0][3] = bias_ex2(s[1][2], s[1][3], bb4[3]);
                #pragma unroll
                for (int cg = 1; cg < 4; cg++)
                    #pragma unroll
                    for (int r = 0; r < 4; r++) pa[cg][r] = 0u;
            }

            // --- O += P @ V, denom += P @ ones (JIT V fragments) ---
            #pragma unroll
            for (int kf = 0; kf < 4; kf++) {
                uint32_t vk[4][2];
                #pragma unroll
                for (int ng = 0; ng < 2; ng++) {
                    uint32_t r4[4];
                    ldm_x4(r4, vbase + (uint32_t)(((ng * 16 + rr) * KST + kf * 16 + ch * 8) * 2));
                    vk[2 * ng][0] = r4[0]; vk[2 * ng][1] = r4[2];
                    vk[2 * ng + 1][0] = r4[1]; vk[2 * ng + 1][1] = r4[3];
                }
                #pragma unroll
                for (int nf = 0; nf < 4; nf++)
                    mma_f16(oacc[bat][nf], pa[kf], vk[nf]);
                mma_f16(c5[bat], pa[kf], bones);
            }
        }
    }

    // --- epilogue: broadcast denominators, normalize, store (per batch) ---
    int src = (lane >> 2) << 2;
    int giA = i0 + w * 16 + (lane >> 2);
    int giB = giA + 8;
    #pragma unroll
    for (int bat = 0; bat < 2; bat++) {
        float l0 = __shfl_sync(0xffffffffu, c5[bat][0], src);
        float l1 = __shfl_sync(0xffffffffu, c5[bat][2], src);
        float inv0 = 1.f / l0, inv1 = 1.f / l1;
        __nv_bfloat16* rb = res + (size_t)(b0 + bat) * HW_ * 256;
        #pragma unroll
        for (int nf = 0; nf < 4; nf++) {
            int col = h * 32 + nf * 8 + (lane & 3) * 2;
            if (giA < HW_)
                *(__nv_bfloat162*)(rb + (size_t)giA * 256 + col) =
                    __floats2bfloat162_rn(oacc[bat][nf][0] * inv0, oacc[bat][nf][1] * inv0);
            if (giB < HW_)
                *(__nv_bfloat162*)(rb + (size_t)giB * 256 + col) =
                    __floats2bfloat162_rn(oacc[bat][nf][2] * inv1, oacc[bat][nf][3] * inv1);
        }
    }
}

// ---------------------------------------------------------------------------
extern "C" void kernel_launch(void* const* d_in, const int* in_sizes, int n_in,
                              void* d_out, int out_size) {
    const float* x     = (const float*)d_in[0];
    const float* Wk_dw = (const float*)d_in[1];
    const float* bk_dw = (const float*)d_in[2];
    const float* Wv_dw = (const float*)d_in[3];
    const float* bv_dw = (const float*)d_in[4];
    const float* Wq    = (const float*)d_in[5];
    const float* bq    = (const float*)d_in[6];
    const float* Wk    = (const float*)d_in[7];
    const float* bk    = (const float*)d_in[8];
    const float* Wv    = (const float*)d_in[9];
    const float* bv    = (const float*)d_in[10];
    const float* Wo    = (const float*)d_in[11];
    const float* bo    = (const float*)d_in[12];
    const float* Bb    = (const float*)d_in[13];
    float* out = (float*)d_out;

    __nv_bfloat16 *qp, *kp, *resp, *xbfp;
    __half *vp, *bbfp;
    __nv_bfloat16 *wqp, *wop;
    float *cqp;
    cudaGetSymbolAddress((void**)&qp,   g_q);
    cudaGetSymbolAddress((void**)&kp,   g_k);
    cudaGetSymbolAddress((void**)&vp,   g_v);
    cudaGetSymbolAddress((void**)&resp, g_res);
    cudaGetSymbolAddress((void**)&xbfp, g_xbf);
    cudaGetSymbolAddress((void**)&bbfp, g_bbf);
    cudaGetSymbolAddress((void**)&wqp,  g_wq);
    cudaGetSymbolAddress((void**)&wop,  g_wo);
    cudaGetSymbolAddress((void**)&cqp,  g_cq);

    cudaFuncSetAttribute(attn_mma_kernel,
                         cudaFuncAttributeMaxDynamicSharedMemorySize, ATT_SMEM);

    cudaStream_t s1, s2;
    cudaStreamCreateWithFlags(&s1, cudaStreamNonBlocking);
    cudaStreamCreateWithFlags(&s2, cudaStreamNonBlocking);
    cudaEvent_t evRoot, evW, ev1, ev2;
    cudaEventCreateWithFlags(&evRoot, cudaEventDisableTiming);
    cudaEventCreateWithFlags(&evW,    cudaEventDisableTiming);
    cudaEventCreateWithFlags(&ev1,    cudaEventDisableTiming);
    cudaEventCreateWithFlags(&ev2,    cudaEventDisableTiming);

    cudaEventRecord(evRoot, 0);
    cudaStreamWaitEvent(s1, evRoot, 0);
    cudaStreamWaitEvent(s2, evRoot, 0);

    // s1: weight conversion first (unblocks everything), then bias conversion
    cvt_w_kernel<<<256, 256, 0, s1>>>(Wq, Wk, Wv, Wo);
    cudaEventRecord(evW, s1);
    cvt_bias<<<BIASN_ / 8 / 256, 256, 0, s1>>>(Bb);
    cudaEventRecord(ev1, s1);

    // s2: dwconv, then fused K+V projections
    dwconv_kernel<<<(B_ * C_ * KHW_ + 255) / 256, 256, 0, s2>>>(x, Wk_dw, bk_dw, Wv_dw, bv_dw);
    cudaStreamWaitEvent(s2, evW, 0);
    gemm_kv<<<dim3(7, 2, 16), 256, 0, s2>>>(bk, bv);
    cudaEventRecord(ev2, s2);

    // main: x conversion + stats, then Q projection
    cvt_x_stats<<<NPART_, 256>>>(x);
    cudaStreamWaitEvent(0, evW, 0);
    stats_final<<<1, 256>>>(bq);
    gemm_wx<<<dim3(25, 2, B_), 256>>>(wqp, xbfp, cqp, 1, HW_, qp);

    cudaStreamWaitEvent(0, ev1, 0);
    cudaStreamWaitEvent(0, ev2, 0);

    attn_mma_kernel<<<dim3(4, HEADS_, 25), 256, ATT_SMEM>>>(qp, kp, vp, bbfp, resp);

    gemm_o<<<dim3(25, 2, B_), 256>>>(resp, wop, bo, x, out);

    cudaEventDestroy(evRoot);
    cudaEventDestroy(evW);
    cudaEventDestroy(ev1);
    cudaEventDestroy(ev2);
    cudaStreamDestroy(s1);
    cudaStreamDestroy(s2);
}